// round 1
// baseline (speedup 1.0000x reference)
#include <cuda_runtime.h>

#define NN 50000
#define EE 1600000
#define H  64
#define EBT 128   // edge-kernel block threads

// ---------------- scratch (device globals; no allocation allowed) ----------------
__device__ float g_h[NN*H];
__device__ float g_A[NN*H];      // h@Wa + e_b1   (also reused as u-buffer in node MLP)
__device__ float g_B[NN*H];      // h@Wb
__device__ float g_magg[NN*H];   // segment-summed messages
__device__ float g_cagg[NN*3];   // segment-summed coord updates
__device__ float g_vel[NN];      // vel_scale
__device__ float g_deg[NN];      // out-degree (as float)
__device__ float g_x[NN*3];
__device__ float g_v[NN*3];

__device__ __forceinline__ float silu_f(float x){
    return __fdividef(x, 1.0f + __expf(-x));
}

// ---------------- init: h = his@emb_w + emb_b ; copy x,v ; zero deg ----------------
__global__ void k_init(const float* __restrict__ his, const float* __restrict__ emb_w,
                       const float* __restrict__ emb_b, const float* __restrict__ x,
                       const float* __restrict__ v){
    int idx = blockIdx.x*blockDim.x + threadIdx.x;
    if (idx < NN*H){
        int n = idx >> 6, j = idx & 63;
        float acc = emb_b[j];
        #pragma unroll
        for (int k=0;k<16;k++) acc += his[n*16+k]*emb_w[k*H+j];
        g_h[idx] = acc;
    }
    if (idx < NN*3){ g_x[idx] = x[idx]; g_v[idx] = v[idx]; }
    if (idx < NN)   g_deg[idx] = 0.0f;
}

__global__ void k_deg(const int* __restrict__ edges){
    int e = blockIdx.x*blockDim.x + threadIdx.x;
    if (e < EE) atomicAdd(&g_deg[edges[e]], 1.0f);
}

// ---------------- per-layer node precompute: A = h@Wa + e_b1, B = h@Wb; zero aggs ----
__global__ void k_pre(const float* __restrict__ e_w1, const float* __restrict__ e_b1){
    __shared__ float s_w[128*H];
    __shared__ float s_b[H];
    int tid = threadIdx.x;
    for (int i=tid; i<128*H; i+=blockDim.x) s_w[i] = e_w1[i];
    if (tid < H) s_b[tid] = e_b1[tid];
    __syncthreads();
    int lane = tid & 31, warp = tid >> 5;
    int j0 = 2*lane;
    int wpb = blockDim.x >> 5;
    for (int n = blockIdx.x*wpb + warp; n < NN; n += gridDim.x*wpb){
        float h0 = g_h[n*H+j0], h1 = g_h[n*H+j0+1];
        float a0 = s_b[j0], a1 = s_b[j0+1], b0 = 0.f, b1 = 0.f;
        #pragma unroll
        for (int k=0;k<H;k++){
            float hk = __shfl_sync(0xffffffffu, (k&1)?h1:h0, k>>1);
            float2 wa = *(const float2*)&s_w[k*H+j0];
            float2 wb = *(const float2*)&s_w[(H+k)*H+j0];
            a0 += hk*wa.x; a1 += hk*wa.y;
            b0 += hk*wb.x; b1 += hk*wb.y;
        }
        *(float2*)&g_A[n*H+j0]    = make_float2(a0,a1);
        *(float2*)&g_B[n*H+j0]    = make_float2(b0,b1);
        *(float2*)&g_magg[n*H+j0] = make_float2(0.f,0.f);
        if (lane < 3) g_cagg[n*3+lane] = 0.f;
    }
}

// ---------------- vel_scale = silu(h@v_w1+v_b1)@v_w2 + v_b2 (uses pre-update h) ----
__global__ void k_vel(const float* __restrict__ v_w1, const float* __restrict__ v_b1,
                      const float* __restrict__ v_w2, const float* __restrict__ v_b2){
    __shared__ float s_w[H*H];
    __shared__ float s_b[H], s_w2s[H];
    int tid = threadIdx.x;
    for (int i=tid; i<H*H; i+=blockDim.x) s_w[i] = v_w1[i];
    if (tid < H){ s_b[tid] = v_b1[tid]; s_w2s[tid] = v_w2[tid]; }
    __syncthreads();
    int lane = tid & 31, warp = tid >> 5;
    int j0 = 2*lane;
    int wpb = blockDim.x >> 5;
    float vb2 = v_b2[0];
    for (int n = blockIdx.x*wpb + warp; n < NN; n += gridDim.x*wpb){
        float h0 = g_h[n*H+j0], h1 = g_h[n*H+j0+1];
        float t0 = s_b[j0], t1 = s_b[j0+1];
        #pragma unroll
        for (int k=0;k<H;k++){
            float hk = __shfl_sync(0xffffffffu, (k&1)?h1:h0, k>>1);
            float2 w = *(const float2*)&s_w[k*H+j0];
            t0 += hk*w.x; t1 += hk*w.y;
        }
        float p = silu_f(t0)*s_w2s[j0] + silu_f(t1)*s_w2s[j0+1];
        #pragma unroll
        for (int o=16;o>0;o>>=1) p += __shfl_xor_sync(0xffffffffu, p, o);
        if (lane == 0) g_vel[n] = p + vb2;
    }
}

// ---------------- edge kernel: thread-per-edge, fused message + coord + scatter ----
__global__ void __launch_bounds__(EBT)
k_edge(const int* __restrict__ edges, const float* __restrict__ edge_attr,
       const float* __restrict__ e_w1, const float* __restrict__ e_w2,
       const float* __restrict__ e_b2, const float* __restrict__ c_w1,
       const float* __restrict__ c_b1, const float* __restrict__ c_w2){
    extern __shared__ float sm[];
    float* s_w2 = sm;                 // 64x64
    float* s_c1 = sm + 4096;          // 64x64
    float* s_t  = sm + 8192;          // 64 x EBT  (per-thread private columns)
    float* s_wr  = sm + 8192 + 64*EBT;
    float* s_we0 = s_wr + 64;
    float* s_we1 = s_wr + 128;
    float* s_eb2 = s_wr + 192;
    float* s_cb1 = s_wr + 256;
    float* s_cw2 = s_wr + 320;
    int tid = threadIdx.x;
    for (int i=tid; i<4096; i+=EBT){ s_w2[i] = e_w2[i]; s_c1[i] = c_w1[i]; }
    if (tid < 64){
        s_wr [tid] = e_w1[128*H+tid];
        s_we0[tid] = e_w1[129*H+tid];
        s_we1[tid] = e_w1[130*H+tid];
        s_eb2[tid] = e_b2[tid];
        s_cb1[tid] = c_b1[tid];
        s_cw2[tid] = c_w2[tid];
    }
    __syncthreads();

    for (int e = blockIdx.x*EBT + tid; e < EE; e += gridDim.x*EBT){
        int r = edges[e], c = edges[EE+e];
        float dx = g_x[3*r+0] - g_x[3*c+0];
        float dy = g_x[3*r+1] - g_x[3*c+1];
        float dz = g_x[3*r+2] - g_x[3*c+2];
        float radial = dx*dx + dy*dy + dz*dz;
        float ea0 = edge_attr[2*e], ea1 = edge_attr[2*e+1];

        // pre = A[r] + B[c] + radial*w_r + ea@W_e  (bias folded into A); t = silu(pre)
        const float4* Ar = (const float4*)&g_A[r*H];
        const float4* Bc = (const float4*)&g_B[c*H];
        #pragma unroll
        for (int jj=0; jj<16; jj++){
            float4 a = Ar[jj], b = Bc[jj];
            int j = jj*4;
            float p0 = a.x + b.x + radial*s_wr[j+0] + ea0*s_we0[j+0] + ea1*s_we1[j+0];
            float p1 = a.y + b.y + radial*s_wr[j+1] + ea0*s_we0[j+1] + ea1*s_we1[j+1];
            float p2 = a.z + b.z + radial*s_wr[j+2] + ea0*s_we0[j+2] + ea1*s_we1[j+2];
            float p3 = a.w + b.w + radial*s_wr[j+3] + ea0*s_we0[j+3] + ea1*s_we1[j+3];
            s_t[(j+0)*EBT+tid] = silu_f(p0);
            s_t[(j+1)*EBT+tid] = silu_f(p1);
            s_t[(j+2)*EBT+tid] = silu_f(p2);
            s_t[(j+3)*EBT+tid] = silu_f(p3);
        }
        // m = silu(t @ e_w2 + e_b2); scatter-add into m_agg[r]
        float m[64];
        #pragma unroll
        for (int j=0;j<64;j++) m[j] = s_eb2[j];
        #pragma unroll 8
        for (int k=0;k<64;k++){
            float tk = s_t[k*EBT+tid];
            const float4* wr = (const float4*)&s_w2[k*H];
            #pragma unroll
            for (int jj=0;jj<16;jj++){
                float4 w = wr[jj];
                m[jj*4+0] += tk*w.x; m[jj*4+1] += tk*w.y;
                m[jj*4+2] += tk*w.z; m[jj*4+3] += tk*w.w;
            }
        }
        int base = r*H;
        #pragma unroll
        for (int j=0;j<64;j++){
            float ms = silu_f(m[j]);
            s_t[j*EBT+tid] = ms;
            atomicAdd(&g_magg[base+j], ms);
        }
        // g = silu(m @ c_w1 + c_b1) @ c_w2 ; coord scatter
        float u[64];
        #pragma unroll
        for (int j=0;j<64;j++) u[j] = s_cb1[j];
        #pragma unroll 8
        for (int k=0;k<64;k++){
            float mk = s_t[k*EBT+tid];
            const float4* wr = (const float4*)&s_c1[k*H];
            #pragma unroll
            for (int jj=0;jj<16;jj++){
                float4 w = wr[jj];
                u[jj*4+0] += mk*w.x; u[jj*4+1] += mk*w.y;
                u[jj*4+2] += mk*w.z; u[jj*4+3] += mk*w.w;
            }
        }
        float g = 0.f;
        #pragma unroll
        for (int j=0;j<64;j++) g += silu_f(u[j])*s_cw2[j];
        atomicAdd(&g_cagg[3*r+0], dx*g);
        atomicAdd(&g_cagg[3*r+1], dy*g);
        atomicAdd(&g_cagg[3*r+2], dz*g);
    }
}

// ---------------- node MLP stage 1: u = silu([h, m_agg]@n_w1 + n_b1) -> g_A -------
__global__ void k_nodeu(const float* __restrict__ n_w1, const float* __restrict__ n_b1){
    __shared__ float s_w[128*H];
    __shared__ float s_b[H];
    int tid = threadIdx.x;
    for (int i=tid; i<128*H; i+=blockDim.x) s_w[i] = n_w1[i];
    if (tid < H) s_b[tid] = n_b1[tid];
    __syncthreads();
    int lane = tid & 31, warp = tid >> 5;
    int j0 = 2*lane;
    int wpb = blockDim.x >> 5;
    for (int n = blockIdx.x*wpb + warp; n < NN; n += gridDim.x*wpb){
        float h0 = g_h[n*H+j0],    h1 = g_h[n*H+j0+1];
        float m0 = g_magg[n*H+j0], m1 = g_magg[n*H+j0+1];
        float u0 = s_b[j0], u1 = s_b[j0+1];
        #pragma unroll
        for (int k=0;k<H;k++){
            float hk = __shfl_sync(0xffffffffu, (k&1)?h1:h0, k>>1);
            float mk = __shfl_sync(0xffffffffu, (k&1)?m1:m0, k>>1);
            float2 w1 = *(const float2*)&s_w[k*H+j0];
            float2 w2 = *(const float2*)&s_w[(H+k)*H+j0];
            u0 += hk*w1.x + mk*w2.x;
            u1 += hk*w1.y + mk*w2.y;
        }
        *(float2*)&g_A[n*H+j0] = make_float2(silu_f(u0), silu_f(u1));
    }
}

// ------- node MLP stage 2 + coord/vel updates: h = 2h + (u@n_w2 + n_b2); v,x ------
__global__ void k_nodefin(const float* __restrict__ n_w2, const float* __restrict__ n_b2){
    __shared__ float s_w[H*H];
    __shared__ float s_b[H];
    int tid = threadIdx.x;
    for (int i=tid; i<H*H; i+=blockDim.x) s_w[i] = n_w2[i];
    if (tid < H) s_b[tid] = n_b2[tid];
    __syncthreads();
    int lane = tid & 31, warp = tid >> 5;
    int j0 = 2*lane;
    int wpb = blockDim.x >> 5;
    for (int n = blockIdx.x*wpb + warp; n < NN; n += gridDim.x*wpb){
        float u0 = g_A[n*H+j0], u1 = g_A[n*H+j0+1];
        float a0 = s_b[j0], a1 = s_b[j0+1];
        #pragma unroll
        for (int k=0;k<H;k++){
            float uk = __shfl_sync(0xffffffffu, (k&1)?u1:u0, k>>1);
            float2 w = *(const float2*)&s_w[k*H+j0];
            a0 += uk*w.x; a1 += uk*w.y;
        }
        float h0 = g_h[n*H+j0], h1 = g_h[n*H+j0+1];
        *(float2*)&g_h[n*H+j0] = make_float2(2.f*h0 + a0, 2.f*h1 + a1);
        if (lane < 3){
            float dg = g_deg[n]; if (dg < 1.f) dg = 1.f;
            float cm = g_cagg[n*3+lane] / dg;
            float vi = g_v[n*3+lane];
            float vn = vi + cm + g_vel[n]*vi;
            g_v[n*3+lane] = vn;
            g_x[n*3+lane] += vn;
        }
    }
}

// ---------------- output: [x (N*3) | h (N*64) | v (N*3)] --------------------------
__global__ void k_out(float* __restrict__ out){
    int i = blockIdx.x*blockDim.x + threadIdx.x;
    if (i < NN*3)            out[i] = g_x[i];
    else if (i < NN*3+NN*H)  out[i] = g_h[i-NN*3];
    else if (i < NN*(6+H))   out[i] = g_v[i-NN*3-NN*H];
}

extern "C" void kernel_launch(void* const* d_in, const int* in_sizes, int n_in,
                              void* d_out, int out_size){
    const float* his  = (const float*)d_in[0];
    const float* x    = (const float*)d_in[1];
    const float* v    = (const float*)d_in[2];
    const float* edge_attr = (const float*)d_in[3];
    const int*   edges= (const int*)  d_in[4];
    const float* emb_w= (const float*)d_in[5];
    const float* emb_b= (const float*)d_in[6];
    const float* e_w1 = (const float*)d_in[7];
    const float* e_b1 = (const float*)d_in[8];
    const float* e_w2 = (const float*)d_in[9];
    const float* e_b2 = (const float*)d_in[10];
    const float* c_w1 = (const float*)d_in[11];
    const float* c_b1 = (const float*)d_in[12];
    const float* c_w2 = (const float*)d_in[13];
    const float* n_w1 = (const float*)d_in[14];
    const float* n_b1 = (const float*)d_in[15];
    const float* n_w2 = (const float*)d_in[16];
    const float* n_b2 = (const float*)d_in[17];
    const float* v_w1 = (const float*)d_in[18];
    const float* v_b1 = (const float*)d_in[19];
    const float* v_w2 = (const float*)d_in[20];
    const float* v_b2 = (const float*)d_in[21];

    const int EDGE_SMEM = (4096 + 4096 + 64*EBT + 384) * 4;  // 67072 B
    cudaFuncSetAttribute(k_edge, cudaFuncAttributeMaxDynamicSharedMemorySize, EDGE_SMEM);

    k_init<<<(NN*H+255)/256, 256>>>(his, emb_w, emb_b, x, v);
    k_deg<<<(EE+255)/256, 256>>>(edges);

    const int gn = 1184;   // node kernels: 8 warps/block, grid-stride
    const int ge = 1776;   // edge kernel: grid-stride

    for (int l=0; l<3; l++){
        k_pre<<<gn, 256>>>(e_w1, e_b1);
        k_vel<<<gn, 256>>>(v_w1, v_b1, v_w2, v_b2);
        k_edge<<<ge, EBT, EDGE_SMEM>>>(edges, edge_attr, e_w1, e_w2, e_b2,
                                       c_w1, c_b1, c_w2);
        k_nodeu<<<gn, 256>>>(n_w1, n_b1);
        k_nodefin<<<gn, 256>>>(n_w2, n_b2);
    }
    k_out<<<(NN*(H+6)+255)/256, 256>>>((float*)d_out);
}

// round 2
// speedup vs baseline: 1.2629x; 1.2629x over previous
#include <cuda_runtime.h>

#define NN 50000
#define EE 1600000
#define H  64
#define EBT 128

typedef unsigned long long ull;

// ---------------- scratch (device globals; no allocation allowed) ----------------
__device__ float g_h[NN*H];
__device__ float g_A[NN*H];      // h@Wa + e_b1
__device__ float g_B[NN*H];      // h@Wb
__device__ float g_magg[NN*H];   // segment-summed messages
__device__ float g_cagg4[NN*4];  // segment-summed coord updates (padded, .w unused)
__device__ float g_vel[NN];      // vel_scale
__device__ float g_deg[NN];      // out-degree
__device__ float g_x4[NN*4];     // padded coords
__device__ float g_v4[NN*4];     // padded velocities

__device__ __forceinline__ float silu_f(float x){
    float th;
    asm("tanh.approx.f32 %0, %1;" : "=f"(th) : "f"(0.5f*x));
    return 0.5f*x*th + 0.5f*x;     // x * sigmoid(x), sigmoid = 0.5*(1+tanh(x/2))
}

__device__ __forceinline__ ull pack2(float x, float y){
    ull r; asm("mov.b64 %0, {%1,%2};" : "=l"(r) : "f"(x), "f"(y)); return r;
}
__device__ __forceinline__ float2 unpack2(ull p){
    float2 r; asm("mov.b64 {%0,%1}, %2;" : "=f"(r.x), "=f"(r.y) : "l"(p)); return r;
}
__device__ __forceinline__ void fma2(ull& d, ull a, ull b){
    asm("fma.rn.f32x2 %0, %1, %2, %0;" : "+l"(d) : "l"(a), "l"(b));
}
__device__ __forceinline__ void red4(float* p, float a, float b, float c, float d){
    asm volatile("red.global.add.v4.f32 [%0], {%1,%2,%3,%4};"
                 :: "l"(p), "f"(a), "f"(b), "f"(c), "f"(d) : "memory");
}

// ---------------- init: h = his@emb_w + emb_b ; pack x,v ; zero deg ---------------
__global__ void k_init(const float* __restrict__ his, const float* __restrict__ emb_w,
                       const float* __restrict__ emb_b, const float* __restrict__ x,
                       const float* __restrict__ v){
    int idx = blockIdx.x*blockDim.x + threadIdx.x;
    if (idx < NN*H){
        int n = idx >> 6, j = idx & 63;
        float acc = emb_b[j];
        #pragma unroll
        for (int k=0;k<16;k++) acc += his[n*16+k]*emb_w[k*H+j];
        g_h[idx] = acc;
    }
    if (idx < NN){
        g_x4[idx*4+0]=x[idx*3+0]; g_x4[idx*4+1]=x[idx*3+1]; g_x4[idx*4+2]=x[idx*3+2]; g_x4[idx*4+3]=0.f;
        g_v4[idx*4+0]=v[idx*3+0]; g_v4[idx*4+1]=v[idx*3+1]; g_v4[idx*4+2]=v[idx*3+2]; g_v4[idx*4+3]=0.f;
        g_deg[idx] = 0.0f;
    }
}

__global__ void k_deg(const int* __restrict__ edges){
    int e = blockIdx.x*blockDim.x + threadIdx.x;
    if (e < EE) atomicAdd(&g_deg[edges[e]], 1.0f);
}

// ------ fused per-layer node precompute: A,B (edge W1 halves), vel_scale; zero aggs
__global__ void k_prevel(const float* __restrict__ e_w1, const float* __restrict__ e_b1,
                         const float* __restrict__ v_w1, const float* __restrict__ v_b1,
                         const float* __restrict__ v_w2, const float* __restrict__ v_b2){
    extern __shared__ float sp[];
    float* s_ew  = sp;            // 128x64
    float* s_vw  = sp + 8192;     // 64x64
    float* s_eb1 = sp + 12288;    // 64
    float* s_vb1 = sp + 12352;    // 64
    float* s_vw2 = sp + 12416;    // 64
    int tid = threadIdx.x;
    for (int i=tid; i<8192; i+=blockDim.x) s_ew[i] = e_w1[i];
    for (int i=tid; i<4096; i+=blockDim.x) s_vw[i] = v_w1[i];
    if (tid < 64){ s_eb1[tid]=e_b1[tid]; s_vb1[tid]=v_b1[tid]; s_vw2[tid]=v_w2[tid]; }
    __syncthreads();
    int lane = tid & 31, warp = tid >> 5;
    int j0 = 2*lane;
    int wpb = blockDim.x >> 5;
    float vb2 = v_b2[0];
    for (int n = blockIdx.x*wpb + warp; n < NN; n += gridDim.x*wpb){
        float h0 = g_h[n*H+j0], h1 = g_h[n*H+j0+1];
        float a0 = s_eb1[j0], a1 = s_eb1[j0+1];
        float b0 = 0.f, b1 = 0.f;
        float t0 = s_vb1[j0], t1 = s_vb1[j0+1];
        #pragma unroll
        for (int k=0;k<H;k++){
            float hk = __shfl_sync(0xffffffffu, (k&1)?h1:h0, k>>1);
            float2 wa = *(const float2*)&s_ew[k*H+j0];
            float2 wb = *(const float2*)&s_ew[(H+k)*H+j0];
            float2 wv = *(const float2*)&s_vw[k*H+j0];
            a0 += hk*wa.x; a1 += hk*wa.y;
            b0 += hk*wb.x; b1 += hk*wb.y;
            t0 += hk*wv.x; t1 += hk*wv.y;
        }
        *(float2*)&g_A[n*H+j0]    = make_float2(a0,a1);
        *(float2*)&g_B[n*H+j0]    = make_float2(b0,b1);
        *(float2*)&g_magg[n*H+j0] = make_float2(0.f,0.f);
        float p = silu_f(t0)*s_vw2[j0] + silu_f(t1)*s_vw2[j0+1];
        #pragma unroll
        for (int o=16;o>0;o>>=1) p += __shfl_xor_sync(0xffffffffu, p, o);
        if (lane == 0){
            g_vel[n] = p + vb2;
            *(float4*)&g_cagg4[n*4] = make_float4(0.f,0.f,0.f,0.f);
        }
    }
}

// ---------------- edge kernel: thread-per-edge, register-t, packed f32x2 FMA ------
__global__ void __launch_bounds__(EBT, 3)
k_edge(const int* __restrict__ edges, const float* __restrict__ edge_attr,
       const float* __restrict__ e_w1, const float* __restrict__ e_w2,
       const float* __restrict__ e_b2, const float* __restrict__ c_w1,
       const float* __restrict__ c_b1, const float* __restrict__ c_w2){
    __shared__ __align__(16) float s_w2[H*H];
    __shared__ __align__(16) float s_c1[H*H];
    __shared__ float s_wr[64], s_we0[64], s_we1[64], s_eb2[64], s_cb1[64], s_cw2[64];
    int tid = threadIdx.x;
    for (int i=tid; i<H*H; i+=EBT){ s_w2[i] = e_w2[i]; s_c1[i] = c_w1[i]; }
    if (tid < 64){
        s_wr [tid] = e_w1[128*H+tid];
        s_we0[tid] = e_w1[129*H+tid];
        s_we1[tid] = e_w1[130*H+tid];
        s_eb2[tid] = e_b2[tid];
        s_cb1[tid] = c_b1[tid];
        s_cw2[tid] = c_w2[tid];
    }
    __syncthreads();

    for (int e = blockIdx.x*EBT + tid; e < EE; e += gridDim.x*EBT){
        int r = edges[e], c = edges[EE+e];
        float4 xr = *(const float4*)&g_x4[r*4];
        float4 xc = *(const float4*)&g_x4[c*4];
        float dx = xr.x-xc.x, dy = xr.y-xc.y, dz = xr.z-xc.z;
        float radial = dx*dx + dy*dy + dz*dz;
        float2 ea = ((const float2*)edge_attr)[e];

        // pre = A[r] + B[c] + radial*w_r + ea@W_e  (bias folded into A); t = silu(pre)
        float t[64];
        const float4* Ar = (const float4*)&g_A[r*H];
        const float4* Bc = (const float4*)&g_B[c*H];
        #pragma unroll
        for (int jj=0; jj<16; jj++){
            float4 a = Ar[jj], b = Bc[jj];
            int j = jj*4;
            t[j+0] = silu_f(a.x + b.x + radial*s_wr[j+0] + ea.x*s_we0[j+0] + ea.y*s_we1[j+0]);
            t[j+1] = silu_f(a.y + b.y + radial*s_wr[j+1] + ea.x*s_we0[j+1] + ea.y*s_we1[j+1]);
            t[j+2] = silu_f(a.z + b.z + radial*s_wr[j+2] + ea.x*s_we0[j+2] + ea.y*s_we1[j+2]);
            t[j+3] = silu_f(a.w + b.w + radial*s_wr[j+3] + ea.x*s_we0[j+3] + ea.y*s_we1[j+3]);
        }

        // m = silu(t @ e_w2 + e_b2)  (packed f32x2 accumulators)
        ull m2[32];
        #pragma unroll
        for (int p=0;p<32;p++) m2[p] = pack2(s_eb2[2*p], s_eb2[2*p+1]);
        #pragma unroll
        for (int k=0;k<64;k++){
            ull tkk = pack2(t[k], t[k]);
            const ulonglong2* wr = (const ulonglong2*)(s_w2 + (k<<6));
            #pragma unroll
            for (int q=0;q<16;q++){
                ulonglong2 w = wr[q];
                fma2(m2[2*q],   tkk, w.x);
                fma2(m2[2*q+1], tkk, w.y);
            }
        }
        // silu(m): scatter to m_agg[r] with v4 reductions; keep for GEMV2 in t[]
        float* magr = &g_magg[r*H];
        #pragma unroll
        for (int g4=0; g4<16; g4++){
            float2 f0 = unpack2(m2[2*g4]);
            float2 f1 = unpack2(m2[2*g4+1]);
            float s0 = silu_f(f0.x), s1 = silu_f(f0.y);
            float s2 = silu_f(f1.x), s3 = silu_f(f1.y);
            t[4*g4+0]=s0; t[4*g4+1]=s1; t[4*g4+2]=s2; t[4*g4+3]=s3;
            red4(magr + 4*g4, s0, s1, s2, s3);
        }

        // g = silu(m @ c_w1 + c_b1) @ c_w2
        ull u2[32];
        #pragma unroll
        for (int p=0;p<32;p++) u2[p] = pack2(s_cb1[2*p], s_cb1[2*p+1]);
        #pragma unroll
        for (int k=0;k<64;k++){
            ull mkk = pack2(t[k], t[k]);
            const ulonglong2* wr = (const ulonglong2*)(s_c1 + (k<<6));
            #pragma unroll
            for (int q=0;q<16;q++){
                ulonglong2 w = wr[q];
                fma2(u2[2*q],   mkk, w.x);
                fma2(u2[2*q+1], mkk, w.y);
            }
        }
        float g = 0.f;
        #pragma unroll
        for (int p=0;p<32;p++){
            float2 f = unpack2(u2[p]);
            g += silu_f(f.x)*s_cw2[2*p] + silu_f(f.y)*s_cw2[2*p+1];
        }
        red4(&g_cagg4[r*4], dx*g, dy*g, dz*g, 0.f);
    }
}

// -------- fused node MLP + state update: h = 2h + (silu([h,m]@W1+b1)@W2 + b2) -----
__global__ void k_node(const float* __restrict__ n_w1, const float* __restrict__ n_b1,
                       const float* __restrict__ n_w2, const float* __restrict__ n_b2){
    extern __shared__ float sn[];
    float* s_w1 = sn;           // 128x64
    float* s_w2 = sn + 8192;    // 64x64
    float* s_b1 = sn + 12288;   // 64
    float* s_b2 = sn + 12352;   // 64
    int tid = threadIdx.x;
    for (int i=tid; i<8192; i+=blockDim.x) s_w1[i] = n_w1[i];
    for (int i=tid; i<4096; i+=blockDim.x) s_w2[i] = n_w2[i];
    if (tid < 64){ s_b1[tid]=n_b1[tid]; s_b2[tid]=n_b2[tid]; }
    __syncthreads();
    int lane = tid & 31, warp = tid >> 5;
    int j0 = 2*lane;
    int wpb = blockDim.x >> 5;
    for (int n = blockIdx.x*wpb + warp; n < NN; n += gridDim.x*wpb){
        float h0 = g_h[n*H+j0],    h1 = g_h[n*H+j0+1];
        float m0 = g_magg[n*H+j0], m1 = g_magg[n*H+j0+1];
        float u0 = s_b1[j0], u1 = s_b1[j0+1];
        #pragma unroll
        for (int k=0;k<H;k++){
            float hk = __shfl_sync(0xffffffffu, (k&1)?h1:h0, k>>1);
            float mk = __shfl_sync(0xffffffffu, (k&1)?m1:m0, k>>1);
            float2 w1 = *(const float2*)&s_w1[k*H+j0];
            float2 w2 = *(const float2*)&s_w1[(H+k)*H+j0];
            u0 += hk*w1.x + mk*w2.x;
            u1 += hk*w1.y + mk*w2.y;
        }
        u0 = silu_f(u0); u1 = silu_f(u1);
        float a0 = s_b2[j0], a1 = s_b2[j0+1];
        #pragma unroll
        for (int k=0;k<H;k++){
            float uk = __shfl_sync(0xffffffffu, (k&1)?u1:u0, k>>1);
            float2 w = *(const float2*)&s_w2[k*H+j0];
            a0 += uk*w.x; a1 += uk*w.y;
        }
        *(float2*)&g_h[n*H+j0] = make_float2(2.f*h0 + a0, 2.f*h1 + a1);
        if (lane < 3){
            float dg = g_deg[n]; if (dg < 1.f) dg = 1.f;
            float cm = g_cagg4[n*4+lane] / dg;
            float vi = g_v4[n*4+lane];
            float vn = vi + cm + g_vel[n]*vi;
            g_v4[n*4+lane] = vn;
            g_x4[n*4+lane] += vn;
        }
    }
}

// ---------------- output: [x (N*3) | h (N*64) | v (N*3)] --------------------------
__global__ void k_out(float* __restrict__ out){
    int i = blockIdx.x*blockDim.x + threadIdx.x;
    if (i < NN*3){
        int n = i/3, d = i - n*3;
        out[i] = g_x4[n*4+d];
    } else if (i < NN*3+NN*H){
        out[i] = g_h[i-NN*3];
    } else if (i < NN*(6+H)){
        int j = i - NN*3 - NN*H;
        int n = j/3, d = j - n*3;
        out[i] = g_v4[n*4+d];
    }
}

extern "C" void kernel_launch(void* const* d_in, const int* in_sizes, int n_in,
                              void* d_out, int out_size){
    const float* his  = (const float*)d_in[0];
    const float* x    = (const float*)d_in[1];
    const float* v    = (const float*)d_in[2];
    const float* edge_attr = (const float*)d_in[3];
    const int*   edges= (const int*)  d_in[4];
    const float* emb_w= (const float*)d_in[5];
    const float* emb_b= (const float*)d_in[6];
    const float* e_w1 = (const float*)d_in[7];
    const float* e_b1 = (const float*)d_in[8];
    const float* e_w2 = (const float*)d_in[9];
    const float* e_b2 = (const float*)d_in[10];
    const float* c_w1 = (const float*)d_in[11];
    const float* c_b1 = (const float*)d_in[12];
    const float* c_w2 = (const float*)d_in[13];
    const float* n_w1 = (const float*)d_in[14];
    const float* n_b1 = (const float*)d_in[15];
    const float* n_w2 = (const float*)d_in[16];
    const float* n_b2 = (const float*)d_in[17];
    const float* v_w1 = (const float*)d_in[18];
    const float* v_b1 = (const float*)d_in[19];
    const float* v_w2 = (const float*)d_in[20];
    const float* v_b2 = (const float*)d_in[21];

    const int PREVEL_SMEM = 12480*4;   // 49920 B
    const int NODE_SMEM   = 12416*4;   // 49664 B
    cudaFuncSetAttribute(k_prevel, cudaFuncAttributeMaxDynamicSharedMemorySize, PREVEL_SMEM);
    cudaFuncSetAttribute(k_node,   cudaFuncAttributeMaxDynamicSharedMemorySize, NODE_SMEM);

    k_init<<<(NN*H+255)/256, 256>>>(his, emb_w, emb_b, x, v);
    k_deg<<<(EE+255)/256, 256>>>(edges);

    const int gn = 1184;   // node kernels: 8 warps/block, grid-stride
    const int ge = 444;    // edge kernel: persistent-ish grid-stride (3 blocks/SM)

    for (int l=0; l<3; l++){
        k_prevel<<<gn, 256, PREVEL_SMEM>>>(e_w1, e_b1, v_w1, v_b1, v_w2, v_b2);
        k_edge<<<ge, EBT>>>(edges, edge_attr, e_w1, e_w2, e_b2, c_w1, c_b1, c_w2);
        k_node<<<gn, 256, NODE_SMEM>>>(n_w1, n_b1, n_w2, n_b2);
    }
    k_out<<<(NN*(H+6)+255)/256, 256>>>((float*)d_out);
}

// round 3
// speedup vs baseline: 1.5155x; 1.2000x over previous
#include <cuda_runtime.h>

#define NN 50000
#define EE 1600000
#define H  64
#define TEE 128     // edges per tile
#define TTH 256     // threads per edge block
#define RL  132     // s_t row length (128 + 4 pad)
#define NT  (EE/TEE)  // 12500 tiles

typedef unsigned long long ull;

// ---------------- scratch (device globals; no allocation allowed) ----------------
__device__ float g_h[NN*H];
__device__ float g_A[NN*H];      // h@Wa + e_b1
__device__ float g_B[NN*H];      // h@Wb
__device__ float g_magg[NN*H];   // segment-summed messages
__device__ float g_cagg4[NN*4];  // segment-summed coord updates (padded)
__device__ float g_vel[NN];      // vel_scale
__device__ float g_deg[NN];      // out-degree
__device__ float g_x4[NN*4];     // padded coords
__device__ float g_v4[NN*4];     // padded velocities

__device__ __forceinline__ float silu_f(float x){
    float th;
    asm("tanh.approx.f32 %0, %1;" : "=f"(th) : "f"(0.5f*x));
    return 0.5f*x*th + 0.5f*x;
}
__device__ __forceinline__ ull pack2(float x, float y){
    ull r; asm("mov.b64 %0, {%1,%2};" : "=l"(r) : "f"(x), "f"(y)); return r;
}
__device__ __forceinline__ float2 unpack2(ull p){
    float2 r; asm("mov.b64 {%0,%1}, %2;" : "=f"(r.x), "=f"(r.y) : "l"(p)); return r;
}
__device__ __forceinline__ void fma2(ull& d, ull a, ull b){
    asm("fma.rn.f32x2 %0, %1, %2, %0;" : "+l"(d) : "l"(a), "l"(b));
}
__device__ __forceinline__ void red4(float* p, float a, float b, float c, float d){
    asm volatile("red.global.add.v4.f32 [%0], {%1,%2,%3,%4};"
                 :: "l"(p), "f"(a), "f"(b), "f"(c), "f"(d) : "memory");
}

// ---------------- init ------------------------------------------------------------
__global__ void k_init(const float* __restrict__ his, const float* __restrict__ emb_w,
                       const float* __restrict__ emb_b, const float* __restrict__ x,
                       const float* __restrict__ v){
    int idx = blockIdx.x*blockDim.x + threadIdx.x;
    if (idx < NN*H){
        int n = idx >> 6, j = idx & 63;
        float acc = emb_b[j];
        #pragma unroll
        for (int k=0;k<16;k++) acc += his[n*16+k]*emb_w[k*H+j];
        g_h[idx] = acc;
    }
    if (idx < NN){
        g_x4[idx*4+0]=x[idx*3+0]; g_x4[idx*4+1]=x[idx*3+1]; g_x4[idx*4+2]=x[idx*3+2]; g_x4[idx*4+3]=0.f;
        g_v4[idx*4+0]=v[idx*3+0]; g_v4[idx*4+1]=v[idx*3+1]; g_v4[idx*4+2]=v[idx*3+2]; g_v4[idx*4+3]=0.f;
        g_deg[idx] = 0.0f;
    }
}

__global__ void k_deg(const int* __restrict__ edges){
    int e = blockIdx.x*blockDim.x + threadIdx.x;
    if (e < EE) atomicAdd(&g_deg[edges[e]], 1.0f);
}

// ------ fused per-layer node precompute: A,B, vel_scale; zero aggs ----------------
__global__ void k_prevel(const float* __restrict__ e_w1, const float* __restrict__ e_b1,
                         const float* __restrict__ v_w1, const float* __restrict__ v_b1,
                         const float* __restrict__ v_w2, const float* __restrict__ v_b2){
    extern __shared__ float sp[];
    float* s_ew  = sp;            // 128x64
    float* s_vw  = sp + 8192;     // 64x64
    float* s_eb1 = sp + 12288;
    float* s_vb1 = sp + 12352;
    float* s_vw2 = sp + 12416;
    int tid = threadIdx.x;
    for (int i=tid; i<8192; i+=blockDim.x) s_ew[i] = e_w1[i];
    for (int i=tid; i<4096; i+=blockDim.x) s_vw[i] = v_w1[i];
    if (tid < 64){ s_eb1[tid]=e_b1[tid]; s_vb1[tid]=v_b1[tid]; s_vw2[tid]=v_w2[tid]; }
    __syncthreads();
    int lane = tid & 31, warp = tid >> 5;
    int j0 = 2*lane;
    int wpb = blockDim.x >> 5;
    float vb2 = v_b2[0];
    for (int n = blockIdx.x*wpb + warp; n < NN; n += gridDim.x*wpb){
        float h0 = g_h[n*H+j0], h1 = g_h[n*H+j0+1];
        float a0 = s_eb1[j0], a1 = s_eb1[j0+1];
        float b0 = 0.f, b1 = 0.f;
        float t0 = s_vb1[j0], t1 = s_vb1[j0+1];
        #pragma unroll
        for (int k=0;k<H;k++){
            float hk = __shfl_sync(0xffffffffu, (k&1)?h1:h0, k>>1);
            float2 wa = *(const float2*)&s_ew[k*H+j0];
            float2 wb = *(const float2*)&s_ew[(H+k)*H+j0];
            float2 wv = *(const float2*)&s_vw[k*H+j0];
            a0 += hk*wa.x; a1 += hk*wa.y;
            b0 += hk*wb.x; b1 += hk*wb.y;
            t0 += hk*wv.x; t1 += hk*wv.y;
        }
        *(float2*)&g_A[n*H+j0]    = make_float2(a0,a1);
        *(float2*)&g_B[n*H+j0]    = make_float2(b0,b1);
        *(float2*)&g_magg[n*H+j0] = make_float2(0.f,0.f);
        float p = silu_f(t0)*s_vw2[j0] + silu_f(t1)*s_vw2[j0+1];
        #pragma unroll
        for (int o=16;o>0;o>>=1) p += __shfl_xor_sync(0xffffffffu, p, o);
        if (lane == 0){
            g_vel[n] = p + vb2;
            *(float4*)&g_cagg4[n*4] = make_float4(0.f,0.f,0.f,0.f);
        }
    }
}

// ---------------- edge kernel: tiled-GEMM phases over 128-edge tiles --------------
__global__ void __launch_bounds__(TTH, 3)
k_edge(const int* __restrict__ edges, const float* __restrict__ edge_attr,
       const float* __restrict__ e_w1, const float* __restrict__ e_w2,
       const float* __restrict__ e_b2, const float* __restrict__ c_w1,
       const float* __restrict__ c_b1, const float* __restrict__ c_w2){
    extern __shared__ float sm[];
    float* s_w2  = sm;              // 4096
    float* s_c1  = sm + 4096;       // 4096
    float* s_t   = sm + 8192;       // 64*RL = 8448
    float* s_gp  = sm + 16640;      // 8*128 = 1024
    float* s_dx  = sm + 17664;      // 128
    float* s_dy  = sm + 17792;
    float* s_dz  = sm + 17920;
    int*   s_r   = (int*)(sm + 18048);  // 128
    float* s_wr  = sm + 18176;
    float* s_we0 = sm + 18240;
    float* s_we1 = sm + 18304;
    float* s_eb2 = sm + 18368;
    float* s_cb1 = sm + 18432;
    float* s_cw2 = sm + 18496;      // end 18560 floats = 74240 B

    int tid = threadIdx.x;
    for (int i=tid; i<4096; i+=TTH){ s_w2[i] = e_w2[i]; s_c1[i] = c_w1[i]; }
    if (tid < 64){
        s_wr [tid] = e_w1[128*H+tid];
        s_we0[tid] = e_w1[129*H+tid];
        s_we1[tid] = e_w1[130*H+tid];
        s_eb2[tid] = e_b2[tid];
        s_cb1[tid] = c_b1[tid];
        s_cw2[tid] = c_w2[tid];
    }
    __syncthreads();

    int el = tid & 127, hf = tid >> 7;           // P1 mapping
    int eg = tid & 31,  og = tid >> 5;           // P2/P3/P4 mapping (og = warp)

    for (int tile = blockIdx.x; tile < NT; tile += gridDim.x){
        // ---- P1: gather + first-layer pre + silu -> s_t[k][e] ----
        {
            int e = tile*TEE + el;
            int r = edges[e], c = edges[EE+e];
            float4 xr = *(const float4*)&g_x4[r*4];
            float4 xc = *(const float4*)&g_x4[c*4];
            float dx = xr.x-xc.x, dy = xr.y-xc.y, dz = xr.z-xc.z;
            float radial = dx*dx + dy*dy + dz*dz;
            float2 ea = ((const float2*)edge_attr)[e];
            const float4* Ap = (const float4*)(g_A + r*H + hf*32);
            const float4* Bp = (const float4*)(g_B + c*H + hf*32);
            int kb = hf*32;
            #pragma unroll
            for (int q=0;q<8;q++){
                float4 a = Ap[q], b = Bp[q];
                int k = kb + 4*q;
                float4 w1 = *(const float4*)&s_wr [k];
                float4 w2 = *(const float4*)&s_we0[k];
                float4 w3 = *(const float4*)&s_we1[k];
                s_t[(k+0)*RL+el] = silu_f(a.x + b.x + radial*w1.x + ea.x*w2.x + ea.y*w3.x);
                s_t[(k+1)*RL+el] = silu_f(a.y + b.y + radial*w1.y + ea.x*w2.y + ea.y*w3.y);
                s_t[(k+2)*RL+el] = silu_f(a.z + b.z + radial*w1.z + ea.x*w2.z + ea.y*w3.z);
                s_t[(k+3)*RL+el] = silu_f(a.w + b.w + radial*w1.w + ea.x*w2.w + ea.y*w3.w);
            }
            if (!hf){ s_r[el]=r; s_dx[el]=dx; s_dy[el]=dy; s_dz[el]=dz; }
        }
        __syncthreads();

        // ---- P2: GEMM1  M[e][j] = sum_k s_t[k][e] * w2[k][j] ----
        ull acc[16];
        {
            ull b0 = *(const ull*)&s_eb2[og*8+0];
            ull b1 = *(const ull*)&s_eb2[og*8+2];
            ull b2 = *(const ull*)&s_eb2[og*8+4];
            ull b3 = *(const ull*)&s_eb2[og*8+6];
            #pragma unroll
            for (int e4=0;e4<4;e4++){ acc[e4*4]=b0; acc[e4*4+1]=b1; acc[e4*4+2]=b2; acc[e4*4+3]=b3; }
            const float* tp = s_t + eg*4;
            const float* wk = s_w2 + og*8;
            #pragma unroll 8
            for (int k=0;k<64;k++){
                float4 tv = *(const float4*)(tp + k*RL);
                ulonglong2 wa = *(const ulonglong2*)(wk + k*64);
                ulonglong2 wb = *(const ulonglong2*)(wk + k*64 + 4);
                ull t0 = pack2(tv.x,tv.x), t1 = pack2(tv.y,tv.y);
                ull t2 = pack2(tv.z,tv.z), t3 = pack2(tv.w,tv.w);
                fma2(acc[0],  t0, wa.x); fma2(acc[1],  t0, wa.y); fma2(acc[2],  t0, wb.x); fma2(acc[3],  t0, wb.y);
                fma2(acc[4],  t1, wa.x); fma2(acc[5],  t1, wa.y); fma2(acc[6],  t1, wb.x); fma2(acc[7],  t1, wb.y);
                fma2(acc[8],  t2, wa.x); fma2(acc[9],  t2, wa.y); fma2(acc[10], t2, wb.x); fma2(acc[11], t2, wb.y);
                fma2(acc[12], t3, wa.x); fma2(acc[13], t3, wa.y); fma2(acc[14], t3, wb.x); fma2(acc[15], t3, wb.y);
            }
        }
        __syncthreads();   // all P2 reads of s_t done before P3 overwrites

        // ---- P3: silu(M), scatter m_agg, store ms -> s_t[j][e] ----
        {
            float ms[4][8];
            #pragma unroll
            for (int e4=0;e4<4;e4++){
                #pragma unroll
                for (int jp=0;jp<4;jp++){
                    float2 f = unpack2(acc[e4*4+jp]);
                    ms[e4][2*jp]   = silu_f(f.x);
                    ms[e4][2*jp+1] = silu_f(f.y);
                }
                int r = s_r[eg*4+e4];
                float* mp = &g_magg[r*H + og*8];
                red4(mp,   ms[e4][0], ms[e4][1], ms[e4][2], ms[e4][3]);
                red4(mp+4, ms[e4][4], ms[e4][5], ms[e4][6], ms[e4][7]);
            }
            #pragma unroll
            for (int j=0;j<8;j++){
                *(float4*)&s_t[(og*8+j)*RL + eg*4] =
                    make_float4(ms[0][j], ms[1][j], ms[2][j], ms[3][j]);
            }
        }
        __syncthreads();

        // ---- P4: GEMM2  U[e][j] = sum_k ms[k][e] * c1[k][j]; partial g ----
        {
            ull b0 = *(const ull*)&s_cb1[og*8+0];
            ull b1 = *(const ull*)&s_cb1[og*8+2];
            ull b2 = *(const ull*)&s_cb1[og*8+4];
            ull b3 = *(const ull*)&s_cb1[og*8+6];
            #pragma unroll
            for (int e4=0;e4<4;e4++){ acc[e4*4]=b0; acc[e4*4+1]=b1; acc[e4*4+2]=b2; acc[e4*4+3]=b3; }
            const float* tp = s_t + eg*4;
            const float* wk = s_c1 + og*8;
            #pragma unroll 8
            for (int k=0;k<64;k++){
                float4 tv = *(const float4*)(tp + k*RL);
                ulonglong2 wa = *(const ulonglong2*)(wk + k*64);
                ulonglong2 wb = *(const ulonglong2*)(wk + k*64 + 4);
                ull t0 = pack2(tv.x,tv.x), t1 = pack2(tv.y,tv.y);
                ull t2 = pack2(tv.z,tv.z), t3 = pack2(tv.w,tv.w);
                fma2(acc[0],  t0, wa.x); fma2(acc[1],  t0, wa.y); fma2(acc[2],  t0, wb.x); fma2(acc[3],  t0, wb.y);
                fma2(acc[4],  t1, wa.x); fma2(acc[5],  t1, wa.y); fma2(acc[6],  t1, wb.x); fma2(acc[7],  t1, wb.y);
                fma2(acc[8],  t2, wa.x); fma2(acc[9],  t2, wa.y); fma2(acc[10], t2, wb.x); fma2(acc[11], t2, wb.y);
                fma2(acc[12], t3, wa.x); fma2(acc[13], t3, wa.y); fma2(acc[14], t3, wb.x); fma2(acc[15], t3, wb.y);
            }
            float gp[4];
            #pragma unroll
            for (int e4=0;e4<4;e4++){
                float s = 0.f;
                #pragma unroll
                for (int jp=0;jp<4;jp++){
                    float2 f = unpack2(acc[e4*4+jp]);
                    s += silu_f(f.x)*s_cw2[og*8+2*jp] + silu_f(f.y)*s_cw2[og*8+2*jp+1];
                }
                gp[e4] = s;
            }
            *(float4*)&s_gp[og*128 + eg*4] = make_float4(gp[0],gp[1],gp[2],gp[3]);
        }
        __syncthreads();

        // ---- P5: reduce g across out-groups, scatter coords ----
        if (tid < 128){
            float g = 0.f;
            #pragma unroll
            for (int o=0;o<8;o++) g += s_gp[o*128 + tid];
            int r = s_r[tid];
            red4(&g_cagg4[r*4], s_dx[tid]*g, s_dy[tid]*g, s_dz[tid]*g, 0.f);
        }
        __syncthreads();   // protect s_t/s_r/s_d/s_gp before next tile's P1
    }
}

// -------- fused node MLP + state update ------------------------------------------
__global__ void k_node(const float* __restrict__ n_w1, const float* __restrict__ n_b1,
                       const float* __restrict__ n_w2, const float* __restrict__ n_b2){
    extern __shared__ float sn[];
    float* s_w1 = sn;           // 128x64
    float* s_w2 = sn + 8192;    // 64x64
    float* s_b1 = sn + 12288;
    float* s_b2 = sn + 12352;
    int tid = threadIdx.x;
    for (int i=tid; i<8192; i+=blockDim.x) s_w1[i] = n_w1[i];
    for (int i=tid; i<4096; i+=blockDim.x) s_w2[i] = n_w2[i];
    if (tid < 64){ s_b1[tid]=n_b1[tid]; s_b2[tid]=n_b2[tid]; }
    __syncthreads();
    int lane = tid & 31, warp = tid >> 5;
    int j0 = 2*lane;
    int wpb = blockDim.x >> 5;
    for (int n = blockIdx.x*wpb + warp; n < NN; n += gridDim.x*wpb){
        float h0 = g_h[n*H+j0],    h1 = g_h[n*H+j0+1];
        float m0 = g_magg[n*H+j0], m1 = g_magg[n*H+j0+1];
        float u0 = s_b1[j0], u1 = s_b1[j0+1];
        #pragma unroll
        for (int k=0;k<H;k++){
            float hk = __shfl_sync(0xffffffffu, (k&1)?h1:h0, k>>1);
            float mk = __shfl_sync(0xffffffffu, (k&1)?m1:m0, k>>1);
            float2 w1 = *(const float2*)&s_w1[k*H+j0];
            float2 w2 = *(const float2*)&s_w1[(H+k)*H+j0];
            u0 += hk*w1.x + mk*w2.x;
            u1 += hk*w1.y + mk*w2.y;
        }
        u0 = silu_f(u0); u1 = silu_f(u1);
        float a0 = s_b2[j0], a1 = s_b2[j0+1];
        #pragma unroll
        for (int k=0;k<H;k++){
            float uk = __shfl_sync(0xffffffffu, (k&1)?u1:u0, k>>1);
            float2 w = *(const float2*)&s_w2[k*H+j0];
            a0 += uk*w.x; a1 += uk*w.y;
        }
        *(float2*)&g_h[n*H+j0] = make_float2(2.f*h0 + a0, 2.f*h1 + a1);
        if (lane < 3){
            float dg = g_deg[n]; if (dg < 1.f) dg = 1.f;
            float cm = g_cagg4[n*4+lane] / dg;
            float vi = g_v4[n*4+lane];
            float vn = vi + cm + g_vel[n]*vi;
            g_v4[n*4+lane] = vn;
            g_x4[n*4+lane] += vn;
        }
    }
}

// ---------------- output: [x | h | v] ---------------------------------------------
__global__ void k_out(float* __restrict__ out){
    int i = blockIdx.x*blockDim.x + threadIdx.x;
    if (i < NN*3){
        int n = i/3, d = i - n*3;
        out[i] = g_x4[n*4+d];
    } else if (i < NN*3+NN*H){
        out[i] = g_h[i-NN*3];
    } else if (i < NN*(6+H)){
        int j = i - NN*3 - NN*H;
        int n = j/3, d = j - n*3;
        out[i] = g_v4[n*4+d];
    }
}

extern "C" void kernel_launch(void* const* d_in, const int* in_sizes, int n_in,
                              void* d_out, int out_size){
    const float* his  = (const float*)d_in[0];
    const float* x    = (const float*)d_in[1];
    const float* v    = (const float*)d_in[2];
    const float* edge_attr = (const float*)d_in[3];
    const int*   edges= (const int*)  d_in[4];
    const float* emb_w= (const float*)d_in[5];
    const float* emb_b= (const float*)d_in[6];
    const float* e_w1 = (const float*)d_in[7];
    const float* e_b1 = (const float*)d_in[8];
    const float* e_w2 = (const float*)d_in[9];
    const float* e_b2 = (const float*)d_in[10];
    const float* c_w1 = (const float*)d_in[11];
    const float* c_b1 = (const float*)d_in[12];
    const float* c_w2 = (const float*)d_in[13];
    const float* n_w1 = (const float*)d_in[14];
    const float* n_b1 = (const float*)d_in[15];
    const float* n_w2 = (const float*)d_in[16];
    const float* n_b2 = (const float*)d_in[17];
    const float* v_w1 = (const float*)d_in[18];
    const float* v_b1 = (const float*)d_in[19];
    const float* v_w2 = (const float*)d_in[20];
    const float* v_b2 = (const float*)d_in[21];

    const int PREVEL_SMEM = 12480*4;
    const int NODE_SMEM   = 12416*4;
    const int EDGE_SMEM   = 18560*4;   // 74240 B
    cudaFuncSetAttribute(k_prevel, cudaFuncAttributeMaxDynamicSharedMemorySize, PREVEL_SMEM);
    cudaFuncSetAttribute(k_node,   cudaFuncAttributeMaxDynamicSharedMemorySize, NODE_SMEM);
    cudaFuncSetAttribute(k_edge,   cudaFuncAttributeMaxDynamicSharedMemorySize, EDGE_SMEM);

    k_init<<<(NN*H+255)/256, 256>>>(his, emb_w, emb_b, x, v);
    k_deg<<<(EE+255)/256, 256>>>(edges);

    const int gn = 1184;
    const int ge = 444;    // 148 SMs x 3 resident blocks

    for (int l=0; l<3; l++){
        k_prevel<<<gn, 256, PREVEL_SMEM>>>(e_w1, e_b1, v_w1, v_b1, v_w2, v_b2);
        k_edge<<<ge, TTH, EDGE_SMEM>>>(edges, edge_attr, e_w1, e_w2, e_b2,
                                       c_w1, c_b1, c_w2);
        k_node<<<gn, 256, NODE_SMEM>>>(n_w1, n_b1, n_w2, n_b2);
    }
    k_out<<<(NN*(H+6)+255)/256, 256>>>((float*)d_out);
}

// round 4
// speedup vs baseline: 1.5378x; 1.0147x over previous
#include <cuda_runtime.h>

#define NN 50000
#define EE 1600000
#define H  64
#define TG  64      // edges per group-tile
#define TTH 256     // threads per edge block (2 groups of 128)
#define RL2 68      // s_t row length (64 + 4 pad, keeps float4 alignment)
#define NTG (EE/TG) // 25000 group-tiles

typedef unsigned long long ull;

// ---------------- scratch (device globals; no allocation allowed) ----------------
__device__ float g_h[NN*H];
__device__ float g_A[NN*H];      // h@Wa + e_b1
__device__ float g_B[NN*H];      // h@Wb
__device__ float g_magg[NN*H];   // segment-summed messages
__device__ float g_cagg4[NN*4];  // segment-summed coord updates (padded)
__device__ float g_vel[NN];      // vel_scale
__device__ float g_deg[NN];      // out-degree
__device__ float g_x4[NN*4];     // padded coords
__device__ float g_v4[NN*4];     // padded velocities

__device__ __forceinline__ float silu_f(float x){
    float th;
    asm("tanh.approx.f32 %0, %1;" : "=f"(th) : "f"(0.5f*x));
    return 0.5f*x*th + 0.5f*x;
}
__device__ __forceinline__ ull pack2(float x, float y){
    ull r; asm("mov.b64 %0, {%1,%2};" : "=l"(r) : "f"(x), "f"(y)); return r;
}
__device__ __forceinline__ float2 unpack2(ull p){
    float2 r; asm("mov.b64 {%0,%1}, %2;" : "=f"(r.x), "=f"(r.y) : "l"(p)); return r;
}
__device__ __forceinline__ void fma2(ull& d, ull a, ull b){
    asm("fma.rn.f32x2 %0, %1, %2, %0;" : "+l"(d) : "l"(a), "l"(b));
}
__device__ __forceinline__ void red4(float* p, float a, float b, float c, float d){
    asm volatile("red.global.add.v4.f32 [%0], {%1,%2,%3,%4};"
                 :: "l"(p), "f"(a), "f"(b), "f"(c), "f"(d) : "memory");
}

// ---------------- init ------------------------------------------------------------
__global__ void k_init(const float* __restrict__ his, const float* __restrict__ emb_w,
                       const float* __restrict__ emb_b, const float* __restrict__ x,
                       const float* __restrict__ v){
    int idx = blockIdx.x*blockDim.x + threadIdx.x;
    if (idx < NN*H){
        int n = idx >> 6, j = idx & 63;
        float acc = emb_b[j];
        #pragma unroll
        for (int k=0;k<16;k++) acc += his[n*16+k]*emb_w[k*H+j];
        g_h[idx] = acc;
    }
    if (idx < NN){
        g_x4[idx*4+0]=x[idx*3+0]; g_x4[idx*4+1]=x[idx*3+1]; g_x4[idx*4+2]=x[idx*3+2]; g_x4[idx*4+3]=0.f;
        g_v4[idx*4+0]=v[idx*3+0]; g_v4[idx*4+1]=v[idx*3+1]; g_v4[idx*4+2]=v[idx*3+2]; g_v4[idx*4+3]=0.f;
        g_deg[idx] = 0.0f;
    }
}

__global__ void k_deg(const int* __restrict__ edges){
    int e = blockIdx.x*blockDim.x + threadIdx.x;
    if (e < EE) atomicAdd(&g_deg[edges[e]], 1.0f);
}

// ------ fused per-layer node precompute: A,B, vel_scale; zero aggs ----------------
__global__ void k_prevel(const float* __restrict__ e_w1, const float* __restrict__ e_b1,
                         const float* __restrict__ v_w1, const float* __restrict__ v_b1,
                         const float* __restrict__ v_w2, const float* __restrict__ v_b2){
    extern __shared__ float sp[];
    float* s_ew  = sp;            // 128x64
    float* s_vw  = sp + 8192;     // 64x64
    float* s_eb1 = sp + 12288;
    float* s_vb1 = sp + 12352;
    float* s_vw2 = sp + 12416;
    int tid = threadIdx.x;
    for (int i=tid; i<8192; i+=blockDim.x) s_ew[i] = e_w1[i];
    for (int i=tid; i<4096; i+=blockDim.x) s_vw[i] = v_w1[i];
    if (tid < 64){ s_eb1[tid]=e_b1[tid]; s_vb1[tid]=v_b1[tid]; s_vw2[tid]=v_w2[tid]; }
    __syncthreads();
    int lane = tid & 31, warp = tid >> 5;
    int j0 = 2*lane;
    int wpb = blockDim.x >> 5;
    float vb2 = v_b2[0];
    for (int n = blockIdx.x*wpb + warp; n < NN; n += gridDim.x*wpb){
        float h0 = g_h[n*H+j0], h1 = g_h[n*H+j0+1];
        float a0 = s_eb1[j0], a1 = s_eb1[j0+1];
        float b0 = 0.f, b1 = 0.f;
        float t0 = s_vb1[j0], t1 = s_vb1[j0+1];
        #pragma unroll
        for (int k=0;k<H;k++){
            float hk = __shfl_sync(0xffffffffu, (k&1)?h1:h0, k>>1);
            float2 wa = *(const float2*)&s_ew[k*H+j0];
            float2 wb = *(const float2*)&s_ew[(H+k)*H+j0];
            float2 wv = *(const float2*)&s_vw[k*H+j0];
            a0 += hk*wa.x; a1 += hk*wa.y;
            b0 += hk*wb.x; b1 += hk*wb.y;
            t0 += hk*wv.x; t1 += hk*wv.y;
        }
        *(float2*)&g_A[n*H+j0]    = make_float2(a0,a1);
        *(float2*)&g_B[n*H+j0]    = make_float2(b0,b1);
        *(float2*)&g_magg[n*H+j0] = make_float2(0.f,0.f);
        float p = silu_f(t0)*s_vw2[j0] + silu_f(t1)*s_vw2[j0+1];
        #pragma unroll
        for (int o=16;o>0;o>>=1) p += __shfl_xor_sync(0xffffffffu, p, o);
        if (lane == 0){
            g_vel[n] = p + vb2;
            *(float4*)&g_cagg4[n*4] = make_float4(0.f,0.f,0.f,0.f);
        }
    }
}

// ------- edge kernel: two independent 128-thread groups, 64-edge tiles, named bars
__global__ void __launch_bounds__(TTH, 3)
k_edge(const int* __restrict__ edges, const float* __restrict__ edge_attr,
       const float* __restrict__ e_w1, const float* __restrict__ e_w2,
       const float* __restrict__ e_b2, const float* __restrict__ c_w1,
       const float* __restrict__ c_b1, const float* __restrict__ c_w2){
    extern __shared__ float sm[];
    float* s_w2  = sm;              // 4096 (block-shared, read-only)
    float* s_c1  = sm + 4096;       // 4096
    float* s_wr  = sm + 8192;       // 64
    float* s_we0 = sm + 8256;
    float* s_we1 = sm + 8320;
    float* s_eb2 = sm + 8384;
    float* s_cb1 = sm + 8448;
    float* s_cw2 = sm + 8512;       // .. 8576
    // per-group area: 5120 floats
    int tid = threadIdx.x;
    int g    = tid >> 7;            // group 0/1
    int gtid = tid & 127;
    float* gb   = sm + 8576 + g*5120;
    float* s_t  = gb;               // 64*RL2 = 4352
    float* s_gp = gb + 4352;        // 8*64 = 512
    float* s_dx = gb + 4864;        // 64
    float* s_dy = gb + 4928;
    float* s_dz = gb + 4992;
    int*   s_r  = (int*)(gb + 5056);// 64   (total 18816 floats = 75264 B)

    for (int i=tid; i<4096; i+=TTH){ s_w2[i] = e_w2[i]; s_c1[i] = c_w1[i]; }
    if (tid < 64){
        s_wr [tid] = e_w1[128*H+tid];
        s_we0[tid] = e_w1[129*H+tid];
        s_we1[tid] = e_w1[130*H+tid];
        s_eb2[tid] = e_b2[tid];
        s_cb1[tid] = c_b1[tid];
        s_cw2[tid] = c_w2[tid];
    }
    __syncthreads();

    int el = gtid & 63, hf = gtid >> 6;   // P1 mapping (2 threads/edge)
    int eg = gtid & 15, og = gtid >> 4;   // GEMM mapping: 4 edges x 8 outputs
    int bar = g + 1;

    for (int tile = blockIdx.x*2 + g; tile < NTG; tile += gridDim.x*2){
        // ---- P1: gather + first-layer pre + silu -> s_t[k][e] ----
        {
            int e = tile*TG + el;
            int r = edges[e], c = edges[EE+e];
            float4 xr = *(const float4*)&g_x4[r*4];
            float4 xc = *(const float4*)&g_x4[c*4];
            float dx = xr.x-xc.x, dy = xr.y-xc.y, dz = xr.z-xc.z;
            float radial = dx*dx + dy*dy + dz*dz;
            float2 ea = ((const float2*)edge_attr)[e];
            const float4* Ap = (const float4*)(g_A + r*H + hf*32);
            const float4* Bp = (const float4*)(g_B + c*H + hf*32);
            int kb = hf*32;
            #pragma unroll
            for (int q=0;q<8;q++){
                float4 a = Ap[q], b = Bp[q];
                int k = kb + 4*q;
                float4 w1 = *(const float4*)&s_wr [k];
                float4 w2 = *(const float4*)&s_we0[k];
                float4 w3 = *(const float4*)&s_we1[k];
                s_t[(k+0)*RL2+el] = silu_f(a.x + b.x + radial*w1.x + ea.x*w2.x + ea.y*w3.x);
                s_t[(k+1)*RL2+el] = silu_f(a.y + b.y + radial*w1.y + ea.x*w2.y + ea.y*w3.y);
                s_t[(k+2)*RL2+el] = silu_f(a.z + b.z + radial*w1.z + ea.x*w2.z + ea.y*w3.z);
                s_t[(k+3)*RL2+el] = silu_f(a.w + b.w + radial*w1.w + ea.x*w2.w + ea.y*w3.w);
            }
            if (!hf){ s_r[el]=r; s_dx[el]=dx; s_dy[el]=dy; s_dz[el]=dz; }
        }
        asm volatile("bar.sync %0, 128;" :: "r"(bar) : "memory");

        // ---- P2: GEMM1  M[e][j] = sum_k s_t[k][e] * w2[k][j] ----
        ull acc[16];
        {
            ull b0 = *(const ull*)&s_eb2[og*8+0];
            ull b1 = *(const ull*)&s_eb2[og*8+2];
            ull b2 = *(const ull*)&s_eb2[og*8+4];
            ull b3 = *(const ull*)&s_eb2[og*8+6];
            #pragma unroll
            for (int e4=0;e4<4;e4++){ acc[e4*4]=b0; acc[e4*4+1]=b1; acc[e4*4+2]=b2; acc[e4*4+3]=b3; }
            const float* tp = s_t + eg*4;
            const float* wk = s_w2 + og*8;
            #pragma unroll 8
            for (int k=0;k<64;k++){
                float4 tv = *(const float4*)(tp + k*RL2);
                ulonglong2 wa = *(const ulonglong2*)(wk + k*64);
                ulonglong2 wb = *(const ulonglong2*)(wk + k*64 + 4);
                ull t0 = pack2(tv.x,tv.x), t1 = pack2(tv.y,tv.y);
                ull t2 = pack2(tv.z,tv.z), t3 = pack2(tv.w,tv.w);
                fma2(acc[0],  t0, wa.x); fma2(acc[1],  t0, wa.y); fma2(acc[2],  t0, wb.x); fma2(acc[3],  t0, wb.y);
                fma2(acc[4],  t1, wa.x); fma2(acc[5],  t1, wa.y); fma2(acc[6],  t1, wb.x); fma2(acc[7],  t1, wb.y);
                fma2(acc[8],  t2, wa.x); fma2(acc[9],  t2, wa.y); fma2(acc[10], t2, wb.x); fma2(acc[11], t2, wb.y);
                fma2(acc[12], t3, wa.x); fma2(acc[13], t3, wa.y); fma2(acc[14], t3, wb.x); fma2(acc[15], t3, wb.y);
            }
        }
        asm volatile("bar.sync %0, 128;" :: "r"(bar) : "memory");

        // ---- P3: silu(M), scatter m_agg, store ms -> s_t[j][e] ----
        {
            float ms[4][8];
            #pragma unroll
            for (int e4=0;e4<4;e4++){
                #pragma unroll
                for (int jp=0;jp<4;jp++){
                    float2 f = unpack2(acc[e4*4+jp]);
                    ms[e4][2*jp]   = silu_f(f.x);
                    ms[e4][2*jp+1] = silu_f(f.y);
                }
                int r = s_r[eg*4+e4];
                float* mp = &g_magg[r*H + og*8];
                red4(mp,   ms[e4][0], ms[e4][1], ms[e4][2], ms[e4][3]);
                red4(mp+4, ms[e4][4], ms[e4][5], ms[e4][6], ms[e4][7]);
            }
            #pragma unroll
            for (int j=0;j<8;j++){
                *(float4*)&s_t[(og*8+j)*RL2 + eg*4] =
                    make_float4(ms[0][j], ms[1][j], ms[2][j], ms[3][j]);
            }
        }
        asm volatile("bar.sync %0, 128;" :: "r"(bar) : "memory");

        // ---- P4: GEMM2  U[e][j] = sum_k ms[k][e] * c1[k][j]; partial g ----
        {
            ull b0 = *(const ull*)&s_cb1[og*8+0];
            ull b1 = *(const ull*)&s_cb1[og*8+2];
            ull b2 = *(const ull*)&s_cb1[og*8+4];
            ull b3 = *(const ull*)&s_cb1[og*8+6];
            #pragma unroll
            for (int e4=0;e4<4;e4++){ acc[e4*4]=b0; acc[e4*4+1]=b1; acc[e4*4+2]=b2; acc[e4*4+3]=b3; }
            const float* tp = s_t + eg*4;
            const float* wk = s_c1 + og*8;
            #pragma unroll 8
            for (int k=0;k<64;k++){
                float4 tv = *(const float4*)(tp + k*RL2);
                ulonglong2 wa = *(const ulonglong2*)(wk + k*64);
                ulonglong2 wb = *(const ulonglong2*)(wk + k*64 + 4);
                ull t0 = pack2(tv.x,tv.x), t1 = pack2(tv.y,tv.y);
                ull t2 = pack2(tv.z,tv.z), t3 = pack2(tv.w,tv.w);
                fma2(acc[0],  t0, wa.x); fma2(acc[1],  t0, wa.y); fma2(acc[2],  t0, wb.x); fma2(acc[3],  t0, wb.y);
                fma2(acc[4],  t1, wa.x); fma2(acc[5],  t1, wa.y); fma2(acc[6],  t1, wb.x); fma2(acc[7],  t1, wb.y);
                fma2(acc[8],  t2, wa.x); fma2(acc[9],  t2, wa.y); fma2(acc[10], t2, wb.x); fma2(acc[11], t2, wb.y);
                fma2(acc[12], t3, wa.x); fma2(acc[13], t3, wa.y); fma2(acc[14], t3, wb.x); fma2(acc[15], t3, wb.y);
            }
            float gp[4];
            #pragma unroll
            for (int e4=0;e4<4;e4++){
                float s = 0.f;
                #pragma unroll
                for (int jp=0;jp<4;jp++){
                    float2 f = unpack2(acc[e4*4+jp]);
                    s += silu_f(f.x)*s_cw2[og*8+2*jp] + silu_f(f.y)*s_cw2[og*8+2*jp+1];
                }
                gp[e4] = s;
            }
            *(float4*)&s_gp[og*64 + eg*4] = make_float4(gp[0],gp[1],gp[2],gp[3]);
        }
        asm volatile("bar.sync %0, 128;" :: "r"(bar) : "memory");

        // ---- P5: reduce g across out-groups, scatter coords ----
        if (gtid < 64){
            float gg = 0.f;
            #pragma unroll
            for (int o=0;o<8;o++) gg += s_gp[o*64 + gtid];
            int r = s_r[gtid];
            red4(&g_cagg4[r*4], s_dx[gtid]*gg, s_dy[gtid]*gg, s_dz[gtid]*gg, 0.f);
        }
        asm volatile("bar.sync %0, 128;" :: "r"(bar) : "memory");
    }
}

// -------- fused node MLP + state update ------------------------------------------
__global__ void k_node(const float* __restrict__ n_w1, const float* __restrict__ n_b1,
                       const float* __restrict__ n_w2, const float* __restrict__ n_b2){
    extern __shared__ float sn[];
    float* s_w1 = sn;           // 128x64
    float* s_w2 = sn + 8192;    // 64x64
    float* s_b1 = sn + 12288;
    float* s_b2 = sn + 12352;
    int tid = threadIdx.x;
    for (int i=tid; i<8192; i+=blockDim.x) s_w1[i] = n_w1[i];
    for (int i=tid; i<4096; i+=blockDim.x) s_w2[i] = n_w2[i];
    if (tid < 64){ s_b1[tid]=n_b1[tid]; s_b2[tid]=n_b2[tid]; }
    __syncthreads();
    int lane = tid & 31, warp = tid >> 5;
    int j0 = 2*lane;
    int wpb = blockDim.x >> 5;
    for (int n = blockIdx.x*wpb + warp; n < NN; n += gridDim.x*wpb){
        float h0 = g_h[n*H+j0],    h1 = g_h[n*H+j0+1];
        float m0 = g_magg[n*H+j0], m1 = g_magg[n*H+j0+1];
        float u0 = s_b1[j0], u1 = s_b1[j0+1];
        #pragma unroll
        for (int k=0;k<H;k++){
            float hk = __shfl_sync(0xffffffffu, (k&1)?h1:h0, k>>1);
            float mk = __shfl_sync(0xffffffffu, (k&1)?m1:m0, k>>1);
            float2 w1 = *(const float2*)&s_w1[k*H+j0];
            float2 w2 = *(const float2*)&s_w1[(H+k)*H+j0];
            u0 += hk*w1.x + mk*w2.x;
            u1 += hk*w1.y + mk*w2.y;
        }
        u0 = silu_f(u0); u1 = silu_f(u1);
        float a0 = s_b2[j0], a1 = s_b2[j0+1];
        #pragma unroll
        for (int k=0;k<H;k++){
            float uk = __shfl_sync(0xffffffffu, (k&1)?u1:u0, k>>1);
            float2 w = *(const float2*)&s_w2[k*H+j0];
            a0 += uk*w.x; a1 += uk*w.y;
        }
        *(float2*)&g_h[n*H+j0] = make_float2(2.f*h0 + a0, 2.f*h1 + a1);
        if (lane < 3){
            float dg = g_deg[n]; if (dg < 1.f) dg = 1.f;
            float cm = g_cagg4[n*4+lane] / dg;
            float vi = g_v4[n*4+lane];
            float vn = vi + cm + g_vel[n]*vi;
            g_v4[n*4+lane] = vn;
            g_x4[n*4+lane] += vn;
        }
    }
}

// ---------------- output: [x | h | v] ---------------------------------------------
__global__ void k_out(float* __restrict__ out){
    int i = blockIdx.x*blockDim.x + threadIdx.x;
    if (i < NN*3){
        int n = i/3, d = i - n*3;
        out[i] = g_x4[n*4+d];
    } else if (i < NN*3+NN*H){
        out[i] = g_h[i-NN*3];
    } else if (i < NN*(6+H)){
        int j = i - NN*3 - NN*H;
        int n = j/3, d = j - n*3;
        out[i] = g_v4[n*4+d];
    }
}

extern "C" void kernel_launch(void* const* d_in, const int* in_sizes, int n_in,
                              void* d_out, int out_size){
    const float* his  = (const float*)d_in[0];
    const float* x    = (const float*)d_in[1];
    const float* v    = (const float*)d_in[2];
    const float* edge_attr = (const float*)d_in[3];
    const int*   edges= (const int*)  d_in[4];
    const float* emb_w= (const float*)d_in[5];
    const float* emb_b= (const float*)d_in[6];
    const float* e_w1 = (const float*)d_in[7];
    const float* e_b1 = (const float*)d_in[8];
    const float* e_w2 = (const float*)d_in[9];
    const float* e_b2 = (const float*)d_in[10];
    const float* c_w1 = (const float*)d_in[11];
    const float* c_b1 = (const float*)d_in[12];
    const float* c_w2 = (const float*)d_in[13];
    const float* n_w1 = (const float*)d_in[14];
    const float* n_b1 = (const float*)d_in[15];
    const float* n_w2 = (const float*)d_in[16];
    const float* n_b2 = (const float*)d_in[17];
    const float* v_w1 = (const float*)d_in[18];
    const float* v_b1 = (const float*)d_in[19];
    const float* v_w2 = (const float*)d_in[20];
    const float* v_b2 = (const float*)d_in[21];

    const int PREVEL_SMEM = 12480*4;
    const int NODE_SMEM   = 12416*4;
    const int EDGE_SMEM   = 18816*4;   // 75264 B
    cudaFuncSetAttribute(k_prevel, cudaFuncAttributeMaxDynamicSharedMemorySize, PREVEL_SMEM);
    cudaFuncSetAttribute(k_node,   cudaFuncAttributeMaxDynamicSharedMemorySize, NODE_SMEM);
    cudaFuncSetAttribute(k_edge,   cudaFuncAttributeMaxDynamicSharedMemorySize, EDGE_SMEM);

    k_init<<<(NN*H+255)/256, 256>>>(his, emb_w, emb_b, x, v);
    k_deg<<<(EE+255)/256, 256>>>(edges);

    const int gn = 1184;
    const int ge = 444;    // 148 SMs x 3 resident blocks (= 888 tile groups)

    for (int l=0; l<3; l++){
        k_prevel<<<gn, 256, PREVEL_SMEM>>>(e_w1, e_b1, v_w1, v_b1, v_w2, v_b2);
        k_edge<<<ge, TTH, EDGE_SMEM>>>(edges, edge_attr, e_w1, e_w2, e_b2,
                                       c_w1, c_b1, c_w2);
        k_node<<<gn, 256, NODE_SMEM>>>(n_w1, n_b1, n_w2, n_b2);
    }
    k_out<<<(NN*(H+6)+255)/256, 256>>>((float*)d_out);
}

// round 5
// speedup vs baseline: 1.5994x; 1.0401x over previous
#include <cuda_runtime.h>

#define NN 50000
#define EE 1600000
#define H  64
#define TG  32      // edges per group-tile
#define GT  64      // threads per group
#define NGB 4       // groups per block
#define TTH 256     // threads per edge block
#define RL3 32      // s_t row length (no pad needed; accesses row-contiguous)
#define NTG (EE/TG) // 50000 group-tiles

typedef unsigned long long ull;

// ---------------- scratch (device globals; no allocation allowed) ----------------
__device__ float g_h[NN*H];
__device__ float g_A[NN*H];      // h@Wa + e_b1
__device__ float g_B[NN*H];      // h@Wb
__device__ float g_magg[NN*H];   // segment-summed messages
__device__ float g_cagg4[NN*4];  // segment-summed coord updates (padded)
__device__ float g_vel[NN];      // vel_scale
__device__ float g_deg[NN];      // out-degree
__device__ float g_x4[NN*4];     // padded coords
__device__ float g_v4[NN*4];     // padded velocities

__device__ __forceinline__ float silu_f(float x){
    float th;
    asm("tanh.approx.f32 %0, %1;" : "=f"(th) : "f"(0.5f*x));
    return 0.5f*x*th + 0.5f*x;
}
__device__ __forceinline__ ull pack2(float x, float y){
    ull r; asm("mov.b64 %0, {%1,%2};" : "=l"(r) : "f"(x), "f"(y)); return r;
}
__device__ __forceinline__ float2 unpack2(ull p){
    float2 r; asm("mov.b64 {%0,%1}, %2;" : "=f"(r.x), "=f"(r.y) : "l"(p)); return r;
}
__device__ __forceinline__ void fma2(ull& d, ull a, ull b){
    asm("fma.rn.f32x2 %0, %1, %2, %0;" : "+l"(d) : "l"(a), "l"(b));
}
__device__ __forceinline__ void red4(float* p, float a, float b, float c, float d){
    asm volatile("red.global.add.v4.f32 [%0], {%1,%2,%3,%4};"
                 :: "l"(p), "f"(a), "f"(b), "f"(c), "f"(d) : "memory");
}

// ---------------- init ------------------------------------------------------------
__global__ void k_init(const float* __restrict__ his, const float* __restrict__ emb_w,
                       const float* __restrict__ emb_b, const float* __restrict__ x,
                       const float* __restrict__ v){
    int idx = blockIdx.x*blockDim.x + threadIdx.x;
    if (idx < NN*H){
        int n = idx >> 6, j = idx & 63;
        float acc = emb_b[j];
        #pragma unroll
        for (int k=0;k<16;k++) acc += his[n*16+k]*emb_w[k*H+j];
        g_h[idx] = acc;
    }
    if (idx < NN){
        g_x4[idx*4+0]=x[idx*3+0]; g_x4[idx*4+1]=x[idx*3+1]; g_x4[idx*4+2]=x[idx*3+2]; g_x4[idx*4+3]=0.f;
        g_v4[idx*4+0]=v[idx*3+0]; g_v4[idx*4+1]=v[idx*3+1]; g_v4[idx*4+2]=v[idx*3+2]; g_v4[idx*4+3]=0.f;
        g_deg[idx] = 0.0f;
    }
}

__global__ void k_deg(const int* __restrict__ edges){
    int e = blockIdx.x*blockDim.x + threadIdx.x;
    if (e < EE) atomicAdd(&g_deg[edges[e]], 1.0f);
}

// ------ fused per-layer node precompute: A,B, vel_scale; zero aggs ----------------
__global__ void k_prevel(const float* __restrict__ e_w1, const float* __restrict__ e_b1,
                         const float* __restrict__ v_w1, const float* __restrict__ v_b1,
                         const float* __restrict__ v_w2, const float* __restrict__ v_b2){
    extern __shared__ float sp[];
    float* s_ew  = sp;            // 128x64
    float* s_vw  = sp + 8192;     // 64x64
    float* s_eb1 = sp + 12288;
    float* s_vb1 = sp + 12352;
    float* s_vw2 = sp + 12416;
    int tid = threadIdx.x;
    for (int i=tid; i<8192; i+=blockDim.x) s_ew[i] = e_w1[i];
    for (int i=tid; i<4096; i+=blockDim.x) s_vw[i] = v_w1[i];
    if (tid < 64){ s_eb1[tid]=e_b1[tid]; s_vb1[tid]=v_b1[tid]; s_vw2[tid]=v_w2[tid]; }
    __syncthreads();
    int lane = tid & 31, warp = tid >> 5;
    int j0 = 2*lane;
    int wpb = blockDim.x >> 5;
    float vb2 = v_b2[0];
    for (int n = blockIdx.x*wpb + warp; n < NN; n += gridDim.x*wpb){
        float h0 = g_h[n*H+j0], h1 = g_h[n*H+j0+1];
        float a0 = s_eb1[j0], a1 = s_eb1[j0+1];
        float b0 = 0.f, b1 = 0.f;
        float t0 = s_vb1[j0], t1 = s_vb1[j0+1];
        #pragma unroll
        for (int k=0;k<H;k++){
            float hk = __shfl_sync(0xffffffffu, (k&1)?h1:h0, k>>1);
            float2 wa = *(const float2*)&s_ew[k*H+j0];
            float2 wb = *(const float2*)&s_ew[(H+k)*H+j0];
            float2 wv = *(const float2*)&s_vw[k*H+j0];
            a0 += hk*wa.x; a1 += hk*wa.y;
            b0 += hk*wb.x; b1 += hk*wb.y;
            t0 += hk*wv.x; t1 += hk*wv.y;
        }
        *(float2*)&g_A[n*H+j0]    = make_float2(a0,a1);
        *(float2*)&g_B[n*H+j0]    = make_float2(b0,b1);
        *(float2*)&g_magg[n*H+j0] = make_float2(0.f,0.f);
        float p = silu_f(t0)*s_vw2[j0] + silu_f(t1)*s_vw2[j0+1];
        #pragma unroll
        for (int o=16;o>0;o>>=1) p += __shfl_xor_sync(0xffffffffu, p, o);
        if (lane == 0){
            g_vel[n] = p + vb2;
            *(float4*)&g_cagg4[n*4] = make_float4(0.f,0.f,0.f,0.f);
        }
    }
}

// ------- edge kernel: four independent 64-thread groups, 32-edge tiles ------------
__global__ void __launch_bounds__(TTH, 3)
k_edge(const int* __restrict__ edges, const float* __restrict__ edge_attr,
       const float* __restrict__ e_w1, const float* __restrict__ e_w2,
       const float* __restrict__ e_b2, const float* __restrict__ c_w1,
       const float* __restrict__ c_b1, const float* __restrict__ c_w2){
    extern __shared__ float sm[];
    float* s_w2  = sm;              // 4096 (block-shared, read-only)
    float* s_c1  = sm + 4096;       // 4096
    float* s_wr  = sm + 8192;       // 64
    float* s_we0 = sm + 8256;
    float* s_we1 = sm + 8320;
    float* s_eb2 = sm + 8384;
    float* s_cb1 = sm + 8448;
    float* s_cw2 = sm + 8512;       // .. 8576
    // per-group area: 2432 floats
    int tid = threadIdx.x;
    int g    = tid >> 6;            // group 0..3
    int gtid = tid & 63;
    float* gb   = sm + 8576 + g*2432;
    float* s_t  = gb;               // 64*RL3 = 2048
    float* s_gp = gb + 2048;        // 8*32 = 256
    float* s_dx = gb + 2304;        // 32
    float* s_dy = gb + 2336;
    float* s_dz = gb + 2368;
    int*   s_r  = (int*)(gb + 2400);// 32  (total 8576 + 4*2432 = 18304 floats = 73216 B)

    for (int i=tid; i<4096; i+=TTH){ s_w2[i] = e_w2[i]; s_c1[i] = c_w1[i]; }
    if (tid < 64){
        s_wr [tid] = e_w1[128*H+tid];
        s_we0[tid] = e_w1[129*H+tid];
        s_we1[tid] = e_w1[130*H+tid];
        s_eb2[tid] = e_b2[tid];
        s_cb1[tid] = c_b1[tid];
        s_cw2[tid] = c_w2[tid];
    }
    __syncthreads();

    int el = gtid & 31, hf = gtid >> 5;   // P1 mapping (2 threads/edge)
    int eg = gtid & 7,  og = gtid >> 3;   // GEMM mapping: 4 edges x 8 outputs
    int bar = g + 1;

    for (int tile = blockIdx.x*NGB + g; tile < NTG; tile += gridDim.x*NGB){
        // ---- P1: gather + first-layer pre + silu -> s_t[k][e] ----
        {
            int e = tile*TG + el;
            int r = edges[e], c = edges[EE+e];
            float4 xr = *(const float4*)&g_x4[r*4];
            float4 xc = *(const float4*)&g_x4[c*4];
            float dx = xr.x-xc.x, dy = xr.y-xc.y, dz = xr.z-xc.z;
            float radial = dx*dx + dy*dy + dz*dz;
            float2 ea = ((const float2*)edge_attr)[e];
            const float4* Ap = (const float4*)(g_A + r*H + hf*32);
            const float4* Bp = (const float4*)(g_B + c*H + hf*32);
            int kb = hf*32;
            #pragma unroll
            for (int q=0;q<8;q++){
                float4 a = Ap[q], b = Bp[q];
                int k = kb + 4*q;
                float4 w1 = *(const float4*)&s_wr [k];
                float4 w2 = *(const float4*)&s_we0[k];
                float4 w3 = *(const float4*)&s_we1[k];
                s_t[(k+0)*RL3+el] = silu_f(a.x + b.x + radial*w1.x + ea.x*w2.x + ea.y*w3.x);
                s_t[(k+1)*RL3+el] = silu_f(a.y + b.y + radial*w1.y + ea.x*w2.y + ea.y*w3.y);
                s_t[(k+2)*RL3+el] = silu_f(a.z + b.z + radial*w1.z + ea.x*w2.z + ea.y*w3.z);
                s_t[(k+3)*RL3+el] = silu_f(a.w + b.w + radial*w1.w + ea.x*w2.w + ea.y*w3.w);
            }
            if (!hf){ s_r[el]=r; s_dx[el]=dx; s_dy[el]=dy; s_dz[el]=dz; }
        }
        asm volatile("bar.sync %0, 64;" :: "r"(bar) : "memory");

        // ---- P2: GEMM1  M[e][j] = sum_k s_t[k][e] * w2[k][j] ----
        ull acc[16];
        {
            ull b0 = *(const ull*)&s_eb2[og*8+0];
            ull b1 = *(const ull*)&s_eb2[og*8+2];
            ull b2 = *(const ull*)&s_eb2[og*8+4];
            ull b3 = *(const ull*)&s_eb2[og*8+6];
            #pragma unroll
            for (int e4=0;e4<4;e4++){ acc[e4*4]=b0; acc[e4*4+1]=b1; acc[e4*4+2]=b2; acc[e4*4+3]=b3; }
            const float* tp = s_t + eg*4;
            const float* wk = s_w2 + og*8;
            #pragma unroll 8
            for (int k=0;k<64;k++){
                float4 tv = *(const float4*)(tp + k*RL3);
                ulonglong2 wa = *(const ulonglong2*)(wk + k*64);
                ulonglong2 wb = *(const ulonglong2*)(wk + k*64 + 4);
                ull t0 = pack2(tv.x,tv.x), t1 = pack2(tv.y,tv.y);
                ull t2 = pack2(tv.z,tv.z), t3 = pack2(tv.w,tv.w);
                fma2(acc[0],  t0, wa.x); fma2(acc[1],  t0, wa.y); fma2(acc[2],  t0, wb.x); fma2(acc[3],  t0, wb.y);
                fma2(acc[4],  t1, wa.x); fma2(acc[5],  t1, wa.y); fma2(acc[6],  t1, wb.x); fma2(acc[7],  t1, wb.y);
                fma2(acc[8],  t2, wa.x); fma2(acc[9],  t2, wa.y); fma2(acc[10], t2, wb.x); fma2(acc[11], t2, wb.y);
                fma2(acc[12], t3, wa.x); fma2(acc[13], t3, wa.y); fma2(acc[14], t3, wb.x); fma2(acc[15], t3, wb.y);
            }
        }
        asm volatile("bar.sync %0, 64;" :: "r"(bar) : "memory");

        // ---- P3: silu(M), scatter m_agg, store ms -> s_t[j][e] ----
        {
            float ms[4][8];
            #pragma unroll
            for (int e4=0;e4<4;e4++){
                #pragma unroll
                for (int jp=0;jp<4;jp++){
                    float2 f = unpack2(acc[e4*4+jp]);
                    ms[e4][2*jp]   = silu_f(f.x);
                    ms[e4][2*jp+1] = silu_f(f.y);
                }
                int r = s_r[eg*4+e4];
                float* mp = &g_magg[r*H + og*8];
                red4(mp,   ms[e4][0], ms[e4][1], ms[e4][2], ms[e4][3]);
                red4(mp+4, ms[e4][4], ms[e4][5], ms[e4][6], ms[e4][7]);
            }
            #pragma unroll
            for (int j=0;j<8;j++){
                *(float4*)&s_t[(og*8+j)*RL3 + eg*4] =
                    make_float4(ms[0][j], ms[1][j], ms[2][j], ms[3][j]);
            }
        }
        asm volatile("bar.sync %0, 64;" :: "r"(bar) : "memory");

        // ---- P4: GEMM2  U[e][j] = sum_k ms[k][e] * c1[k][j]; partial g ----
        {
            ull b0 = *(const ull*)&s_cb1[og*8+0];
            ull b1 = *(const ull*)&s_cb1[og*8+2];
            ull b2 = *(const ull*)&s_cb1[og*8+4];
            ull b3 = *(const ull*)&s_cb1[og*8+6];
            #pragma unroll
            for (int e4=0;e4<4;e4++){ acc[e4*4]=b0; acc[e4*4+1]=b1; acc[e4*4+2]=b2; acc[e4*4+3]=b3; }
            const float* tp = s_t + eg*4;
            const float* wk = s_c1 + og*8;
            #pragma unroll 8
            for (int k=0;k<64;k++){
                float4 tv = *(const float4*)(tp + k*RL3);
                ulonglong2 wa = *(const ulonglong2*)(wk + k*64);
                ulonglong2 wb = *(const ulonglong2*)(wk + k*64 + 4);
                ull t0 = pack2(tv.x,tv.x), t1 = pack2(tv.y,tv.y);
                ull t2 = pack2(tv.z,tv.z), t3 = pack2(tv.w,tv.w);
                fma2(acc[0],  t0, wa.x); fma2(acc[1],  t0, wa.y); fma2(acc[2],  t0, wb.x); fma2(acc[3],  t0, wb.y);
                fma2(acc[4],  t1, wa.x); fma2(acc[5],  t1, wa.y); fma2(acc[6],  t1, wb.x); fma2(acc[7],  t1, wb.y);
                fma2(acc[8],  t2, wa.x); fma2(acc[9],  t2, wa.y); fma2(acc[10], t2, wb.x); fma2(acc[11], t2, wb.y);
                fma2(acc[12], t3, wa.x); fma2(acc[13], t3, wa.y); fma2(acc[14], t3, wb.x); fma2(acc[15], t3, wb.y);
            }
            float gp[4];
            #pragma unroll
            for (int e4=0;e4<4;e4++){
                float s = 0.f;
                #pragma unroll
                for (int jp=0;jp<4;jp++){
                    float2 f = unpack2(acc[e4*4+jp]);
                    s += silu_f(f.x)*s_cw2[og*8+2*jp] + silu_f(f.y)*s_cw2[og*8+2*jp+1];
                }
                gp[e4] = s;
            }
            *(float4*)&s_gp[og*32 + eg*4] = make_float4(gp[0],gp[1],gp[2],gp[3]);
        }
        asm volatile("bar.sync %0, 64;" :: "r"(bar) : "memory");

        // ---- P5: reduce g across out-groups, scatter coords ----
        if (gtid < 32){
            float gg = 0.f;
            #pragma unroll
            for (int o=0;o<8;o++) gg += s_gp[o*32 + gtid];
            int r = s_r[gtid];
            red4(&g_cagg4[r*4], s_dx[gtid]*gg, s_dy[gtid]*gg, s_dz[gtid]*gg, 0.f);
        }
        asm volatile("bar.sync %0, 64;" :: "r"(bar) : "memory");
    }
}

// -------- fused node MLP + state update ------------------------------------------
__global__ void k_node(const float* __restrict__ n_w1, const float* __restrict__ n_b1,
                       const float* __restrict__ n_w2, const float* __restrict__ n_b2){
    extern __shared__ float sn[];
    float* s_w1 = sn;           // 128x64
    float* s_w2 = sn + 8192;    // 64x64
    float* s_b1 = sn + 12288;
    float* s_b2 = sn + 12352;
    int tid = threadIdx.x;
    for (int i=tid; i<8192; i+=blockDim.x) s_w1[i] = n_w1[i];
    for (int i=tid; i<4096; i+=blockDim.x) s_w2[i] = n_w2[i];
    if (tid < 64){ s_b1[tid]=n_b1[tid]; s_b2[tid]=n_b2[tid]; }
    __syncthreads();
    int lane = tid & 31, warp = tid >> 5;
    int j0 = 2*lane;
    int wpb = blockDim.x >> 5;
    for (int n = blockIdx.x*wpb + warp; n < NN; n += gridDim.x*wpb){
        float h0 = g_h[n*H+j0],    h1 = g_h[n*H+j0+1];
        float m0 = g_magg[n*H+j0], m1 = g_magg[n*H+j0+1];
        float u0 = s_b1[j0], u1 = s_b1[j0+1];
        #pragma unroll
        for (int k=0;k<H;k++){
            float hk = __shfl_sync(0xffffffffu, (k&1)?h1:h0, k>>1);
            float mk = __shfl_sync(0xffffffffu, (k&1)?m1:m0, k>>1);
            float2 w1 = *(const float2*)&s_w1[k*H+j0];
            float2 w2 = *(const float2*)&s_w1[(H+k)*H+j0];
            u0 += hk*w1.x + mk*w2.x;
            u1 += hk*w1.y + mk*w2.y;
        }
        u0 = silu_f(u0); u1 = silu_f(u1);
        float a0 = s_b2[j0], a1 = s_b2[j0+1];
        #pragma unroll
        for (int k=0;k<H;k++){
            float uk = __shfl_sync(0xffffffffu, (k&1)?u1:u0, k>>1);
            float2 w = *(const float2*)&s_w2[k*H+j0];
            a0 += uk*w.x; a1 += uk*w.y;
        }
        *(float2*)&g_h[n*H+j0] = make_float2(2.f*h0 + a0, 2.f*h1 + a1);
        if (lane < 3){
            float dg = g_deg[n]; if (dg < 1.f) dg = 1.f;
            float cm = g_cagg4[n*4+lane] / dg;
            float vi = g_v4[n*4+lane];
            float vn = vi + cm + g_vel[n]*vi;
            g_v4[n*4+lane] = vn;
            g_x4[n*4+lane] += vn;
        }
    }
}

// ---------------- output: [x | h | v] ---------------------------------------------
__global__ void k_out(float* __restrict__ out){
    int i = blockIdx.x*blockDim.x + threadIdx.x;
    if (i < NN*3){
        int n = i/3, d = i - n*3;
        out[i] = g_x4[n*4+d];
    } else if (i < NN*3+NN*H){
        out[i] = g_h[i-NN*3];
    } else if (i < NN*(6+H)){
        int j = i - NN*3 - NN*H;
        int n = j/3, d = j - n*3;
        out[i] = g_v4[n*4+d];
    }
}

extern "C" void kernel_launch(void* const* d_in, const int* in_sizes, int n_in,
                              void* d_out, int out_size){
    const float* his  = (const float*)d_in[0];
    const float* x    = (const float*)d_in[1];
    const float* v    = (const float*)d_in[2];
    const float* edge_attr = (const float*)d_in[3];
    const int*   edges= (const int*)  d_in[4];
    const float* emb_w= (const float*)d_in[5];
    const float* emb_b= (const float*)d_in[6];
    const float* e_w1 = (const float*)d_in[7];
    const float* e_b1 = (const float*)d_in[8];
    const float* e_w2 = (const float*)d_in[9];
    const float* e_b2 = (const float*)d_in[10];
    const float* c_w1 = (const float*)d_in[11];
    const float* c_b1 = (const float*)d_in[12];
    const float* c_w2 = (const float*)d_in[13];
    const float* n_w1 = (const float*)d_in[14];
    const float* n_b1 = (const float*)d_in[15];
    const float* n_w2 = (const float*)d_in[16];
    const float* n_b2 = (const float*)d_in[17];
    const float* v_w1 = (const float*)d_in[18];
    const float* v_b1 = (const float*)d_in[19];
    const float* v_w2 = (const float*)d_in[20];
    const float* v_b2 = (const float*)d_in[21];

    const int PREVEL_SMEM = 12480*4;
    const int NODE_SMEM   = 12416*4;
    const int EDGE_SMEM   = 18304*4;   // 73216 B
    cudaFuncSetAttribute(k_prevel, cudaFuncAttributeMaxDynamicSharedMemorySize, PREVEL_SMEM);
    cudaFuncSetAttribute(k_node,   cudaFuncAttributeMaxDynamicSharedMemorySize, NODE_SMEM);
    cudaFuncSetAttribute(k_edge,   cudaFuncAttributeMaxDynamicSharedMemorySize, EDGE_SMEM);

    k_init<<<(NN*H+255)/256, 256>>>(his, emb_w, emb_b, x, v);
    k_deg<<<(EE+255)/256, 256>>>(edges);

    const int gn = 1184;
    const int ge = 444;    // 148 SMs x 3 resident blocks (= 1776 tile groups)

    for (int l=0; l<3; l++){
        k_prevel<<<gn, 256, PREVEL_SMEM>>>(e_w1, e_b1, v_w1, v_b1, v_w2, v_b2);
        k_edge<<<ge, TTH, EDGE_SMEM>>>(edges, edge_attr, e_w1, e_w2, e_b2,
                                       c_w1, c_b1, c_w2);
        k_node<<<gn, 256, NODE_SMEM>>>(n_w1, n_b1, n_w2, n_b2);
    }
    k_out<<<(NN*(H+6)+255)/256, 256>>>((float*)d_out);
}

// round 6
// speedup vs baseline: 1.7723x; 1.1081x over previous
#include <cuda_runtime.h>

#define NN 50000
#define EE 1600000
#define H  64
#define TG  32      // edges per group-tile
#define NGB 4       // groups per block
#define TTH 256     // threads per edge block
#define RL3 32      // s_t row length
#define NTG (EE/TG) // 50000 group-tiles

typedef unsigned long long ull;

// ---------------- scratch (device globals; no allocation allowed) ----------------
__device__ float g_h[NN*H];
__device__ float g_A[NN*H];      // h@Wa + e_b1
__device__ float g_B[NN*H];      // h@Wb
__device__ float g_magg[NN*H];   // segment-summed messages
__device__ float g_cagg4[NN*4];  // segment-summed coord updates (padded)
__device__ float g_vel[NN];      // vel_scale
__device__ float g_deg[NN];      // clipped out-degree (float)
__device__ int   g_cnt[NN];      // raw out-degree
__device__ int   g_off[NN];      // fill cursors (exclusive prefix, then consumed)
__device__ float g_x4[NN*4];     // padded coords
__device__ float g_v4[NN*4];     // padded velocities
// r-sorted edge arrays
__device__ int    g_er[EE];
__device__ int    g_ec[EE];
__device__ float2 g_ea2[EE];

__device__ __forceinline__ float silu_f(float x){
    float th;
    asm("tanh.approx.f32 %0, %1;" : "=f"(th) : "f"(0.5f*x));
    return 0.5f*x*th + 0.5f*x;
}
__device__ __forceinline__ ull pack2(float x, float y){
    ull r; asm("mov.b64 %0, {%1,%2};" : "=l"(r) : "f"(x), "f"(y)); return r;
}
__device__ __forceinline__ float2 unpack2(ull p){
    float2 r; asm("mov.b64 {%0,%1}, %2;" : "=f"(r.x), "=f"(r.y) : "l"(p)); return r;
}
__device__ __forceinline__ void fma2(ull& d, ull a, ull b){
    asm("fma.rn.f32x2 %0, %1, %2, %0;" : "+l"(d) : "l"(a), "l"(b));
}
__device__ __forceinline__ void red4(float* p, float a, float b, float c, float d){
    asm volatile("red.global.add.v4.f32 [%0], {%1,%2,%3,%4};"
                 :: "l"(p), "f"(a), "f"(b), "f"(c), "f"(d) : "memory");
}

// ---------------- init ------------------------------------------------------------
__global__ void k_init(const float* __restrict__ his, const float* __restrict__ emb_w,
                       const float* __restrict__ emb_b, const float* __restrict__ x,
                       const float* __restrict__ v){
    int idx = blockIdx.x*blockDim.x + threadIdx.x;
    if (idx < NN*H){
        int n = idx >> 6, j = idx & 63;
        float acc = emb_b[j];
        #pragma unroll
        for (int k=0;k<16;k++) acc += his[n*16+k]*emb_w[k*H+j];
        g_h[idx] = acc;
    }
    if (idx < NN){
        g_x4[idx*4+0]=x[idx*3+0]; g_x4[idx*4+1]=x[idx*3+1]; g_x4[idx*4+2]=x[idx*3+2]; g_x4[idx*4+3]=0.f;
        g_v4[idx*4+0]=v[idx*3+0]; g_v4[idx*4+1]=v[idx*3+1]; g_v4[idx*4+2]=v[idx*3+2]; g_v4[idx*4+3]=0.f;
        g_cnt[idx] = 0;
    }
}

__global__ void k_deg(const int* __restrict__ edges){
    int e = blockIdx.x*blockDim.x + threadIdx.x;
    if (e < EE) atomicAdd(&g_cnt[edges[e]], 1);
}

// single-block exclusive scan over g_cnt -> g_off; also g_deg = max(cnt,1)
__global__ void k_scan(){
    __shared__ int s_part[1024];
    int tid = threadIdx.x;
    const int CH = (NN + 1023)/1024;   // 49
    int base = tid*CH;
    int sum = 0;
    #pragma unroll 7
    for (int i=0;i<CH;i++){ int n=base+i; if(n<NN) sum += g_cnt[n]; }
    s_part[tid] = sum;
    __syncthreads();
    for (int off=1; off<1024; off<<=1){
        int t = (tid >= off) ? s_part[tid-off] : 0;
        __syncthreads();
        s_part[tid] += t;
        __syncthreads();
    }
    int run = s_part[tid] - sum;   // exclusive prefix of this chunk
    for (int i=0;i<CH;i++){
        int n = base+i;
        if (n < NN){
            int c = g_cnt[n];
            g_off[n] = run;
            g_deg[n] = (c > 0) ? (float)c : 1.0f;
            run += c;
        }
    }
}

__global__ void k_fill(const int* __restrict__ edges, const float* __restrict__ edge_attr){
    int e = blockIdx.x*blockDim.x + threadIdx.x;
    if (e < EE){
        int r = edges[e];
        int pos = atomicAdd(&g_off[r], 1);
        g_er[pos] = r;
        g_ec[pos] = edges[EE+e];
        g_ea2[pos] = ((const float2*)edge_attr)[e];
    }
}

// ------ fused per-layer node precompute: A,B, vel_scale; zero aggs ----------------
__global__ void k_prevel(const float* __restrict__ e_w1, const float* __restrict__ e_b1,
                         const float* __restrict__ v_w1, const float* __restrict__ v_b1,
                         const float* __restrict__ v_w2, const float* __restrict__ v_b2){
    extern __shared__ float sp[];
    float* s_ew  = sp;            // 128x64
    float* s_vw  = sp + 8192;     // 64x64
    float* s_eb1 = sp + 12288;
    float* s_vb1 = sp + 12352;
    float* s_vw2 = sp + 12416;
    int tid = threadIdx.x;
    for (int i=tid; i<8192; i+=blockDim.x) s_ew[i] = e_w1[i];
    for (int i=tid; i<4096; i+=blockDim.x) s_vw[i] = v_w1[i];
    if (tid < 64){ s_eb1[tid]=e_b1[tid]; s_vb1[tid]=v_b1[tid]; s_vw2[tid]=v_w2[tid]; }
    __syncthreads();
    int lane = tid & 31, warp = tid >> 5;
    int j0 = 2*lane;
    int wpb = blockDim.x >> 5;
    float vb2 = v_b2[0];
    for (int n = blockIdx.x*wpb + warp; n < NN; n += gridDim.x*wpb){
        float h0 = g_h[n*H+j0], h1 = g_h[n*H+j0+1];
        float a0 = s_eb1[j0], a1 = s_eb1[j0+1];
        float b0 = 0.f, b1 = 0.f;
        float t0 = s_vb1[j0], t1 = s_vb1[j0+1];
        #pragma unroll
        for (int k=0;k<H;k++){
            float hk = __shfl_sync(0xffffffffu, (k&1)?h1:h0, k>>1);
            float2 wa = *(const float2*)&s_ew[k*H+j0];
            float2 wb = *(const float2*)&s_ew[(H+k)*H+j0];
            float2 wv = *(const float2*)&s_vw[k*H+j0];
            a0 += hk*wa.x; a1 += hk*wa.y;
            b0 += hk*wb.x; b1 += hk*wb.y;
            t0 += hk*wv.x; t1 += hk*wv.y;
        }
        *(float2*)&g_A[n*H+j0]    = make_float2(a0,a1);
        *(float2*)&g_B[n*H+j0]    = make_float2(b0,b1);
        *(float2*)&g_magg[n*H+j0] = make_float2(0.f,0.f);
        float p = silu_f(t0)*s_vw2[j0] + silu_f(t1)*s_vw2[j0+1];
        #pragma unroll
        for (int o=16;o>0;o>>=1) p += __shfl_xor_sync(0xffffffffu, p, o);
        if (lane == 0){
            g_vel[n] = p + vb2;
            *(float4*)&g_cagg4[n*4] = make_float4(0.f,0.f,0.f,0.f);
        }
    }
}

// ------- edge kernel: four independent 64-thread groups, 32-edge tiles (r-sorted) -
__global__ void __launch_bounds__(TTH, 3)
k_edge(const float* __restrict__ e_w1, const float* __restrict__ e_w2,
       const float* __restrict__ e_b2, const float* __restrict__ c_w1,
       const float* __restrict__ c_b1, const float* __restrict__ c_w2){
    extern __shared__ float sm[];
    float* s_w2  = sm;              // 4096 (block-shared, read-only)
    float* s_c1  = sm + 4096;       // 4096
    float* s_wr  = sm + 8192;       // 64
    float* s_we0 = sm + 8256;
    float* s_we1 = sm + 8320;
    float* s_eb2 = sm + 8384;
    float* s_cb1 = sm + 8448;
    float* s_cw2 = sm + 8512;       // .. 8576
    int tid = threadIdx.x;
    int g    = tid >> 6;            // group 0..3
    int gtid = tid & 63;
    float* gb   = sm + 8576 + g*2432;
    float* s_t  = gb;               // 64*RL3 = 2048
    float* s_gp = gb + 2048;        // 8*32 = 256
    float* s_dx = gb + 2304;        // 32
    float* s_dy = gb + 2336;
    float* s_dz = gb + 2368;
    int*   s_r  = (int*)(gb + 2400);// 32

    for (int i=tid; i<4096; i+=TTH){ s_w2[i] = e_w2[i]; s_c1[i] = c_w1[i]; }
    if (tid < 64){
        s_wr [tid] = e_w1[128*H+tid];
        s_we0[tid] = e_w1[129*H+tid];
        s_we1[tid] = e_w1[130*H+tid];
        s_eb2[tid] = e_b2[tid];
        s_cb1[tid] = c_b1[tid];
        s_cw2[tid] = c_w2[tid];
    }
    __syncthreads();

    int el = gtid & 31, hf = gtid >> 5;   // P1 mapping (2 threads/edge)
    int eg = gtid & 7,  og = gtid >> 3;   // GEMM mapping: 4 edges x 8 outputs
    int bar = g + 1;

    for (int tile = blockIdx.x*NGB + g; tile < NTG; tile += gridDim.x*NGB){
        // ---- P1: gather + first-layer pre + silu -> s_t[k][e] ----
        {
            int e = tile*TG + el;
            int r = g_er[e], c = g_ec[e];
            float4 xr = *(const float4*)&g_x4[r*4];
            float4 xc = *(const float4*)&g_x4[c*4];
            float dx = xr.x-xc.x, dy = xr.y-xc.y, dz = xr.z-xc.z;
            float radial = dx*dx + dy*dy + dz*dz;
            float2 ea = g_ea2[e];
            const float4* Ap = (const float4*)(g_A + r*H + hf*32);
            const float4* Bp = (const float4*)(g_B + c*H + hf*32);
            int kb = hf*32;
            #pragma unroll
            for (int q=0;q<8;q++){
                float4 a = Ap[q], b = Bp[q];
                int k = kb + 4*q;
                float4 w1 = *(const float4*)&s_wr [k];
                float4 w2 = *(const float4*)&s_we0[k];
                float4 w3 = *(const float4*)&s_we1[k];
                s_t[(k+0)*RL3+el] = silu_f(a.x + b.x + radial*w1.x + ea.x*w2.x + ea.y*w3.x);
                s_t[(k+1)*RL3+el] = silu_f(a.y + b.y + radial*w1.y + ea.x*w2.y + ea.y*w3.y);
                s_t[(k+2)*RL3+el] = silu_f(a.z + b.z + radial*w1.z + ea.x*w2.z + ea.y*w3.z);
                s_t[(k+3)*RL3+el] = silu_f(a.w + b.w + radial*w1.w + ea.x*w2.w + ea.y*w3.w);
            }
            if (!hf){ s_r[el]=r; s_dx[el]=dx; s_dy[el]=dy; s_dz[el]=dz; }
        }
        asm volatile("bar.sync %0, 64;" :: "r"(bar) : "memory");

        // ---- P2: GEMM1  M[e][j] = sum_k s_t[k][e] * w2[k][j] ----
        ull acc[16];
        {
            ull b0 = *(const ull*)&s_eb2[og*8+0];
            ull b1 = *(const ull*)&s_eb2[og*8+2];
            ull b2 = *(const ull*)&s_eb2[og*8+4];
            ull b3 = *(const ull*)&s_eb2[og*8+6];
            #pragma unroll
            for (int e4=0;e4<4;e4++){ acc[e4*4]=b0; acc[e4*4+1]=b1; acc[e4*4+2]=b2; acc[e4*4+3]=b3; }
            const float* tp = s_t + eg*4;
            const float* wk = s_w2 + og*8;
            #pragma unroll 8
            for (int k=0;k<64;k++){
                float4 tv = *(const float4*)(tp + k*RL3);
                ulonglong2 wa = *(const ulonglong2*)(wk + k*64);
                ulonglong2 wb = *(const ulonglong2*)(wk + k*64 + 4);
                ull t0 = pack2(tv.x,tv.x), t1 = pack2(tv.y,tv.y);
                ull t2 = pack2(tv.z,tv.z), t3 = pack2(tv.w,tv.w);
                fma2(acc[0],  t0, wa.x); fma2(acc[1],  t0, wa.y); fma2(acc[2],  t0, wb.x); fma2(acc[3],  t0, wb.y);
                fma2(acc[4],  t1, wa.x); fma2(acc[5],  t1, wa.y); fma2(acc[6],  t1, wb.x); fma2(acc[7],  t1, wb.y);
                fma2(acc[8],  t2, wa.x); fma2(acc[9],  t2, wa.y); fma2(acc[10], t2, wb.x); fma2(acc[11], t2, wb.y);
                fma2(acc[12], t3, wa.x); fma2(acc[13], t3, wa.y); fma2(acc[14], t3, wb.x); fma2(acc[15], t3, wb.y);
            }
        }
        asm volatile("bar.sync %0, 64;" :: "r"(bar) : "memory");

        // ---- P3: silu(M), scatter m_agg, store ms -> s_t[j][e] ----
        {
            float ms[4][8];
            #pragma unroll
            for (int e4=0;e4<4;e4++){
                #pragma unroll
                for (int jp=0;jp<4;jp++){
                    float2 f = unpack2(acc[e4*4+jp]);
                    ms[e4][2*jp]   = silu_f(f.x);
                    ms[e4][2*jp+1] = silu_f(f.y);
                }
                int r = s_r[eg*4+e4];
                float* mp = &g_magg[r*H + og*8];
                red4(mp,   ms[e4][0], ms[e4][1], ms[e4][2], ms[e4][3]);
                red4(mp+4, ms[e4][4], ms[e4][5], ms[e4][6], ms[e4][7]);
            }
            #pragma unroll
            for (int j=0;j<8;j++){
                *(float4*)&s_t[(og*8+j)*RL3 + eg*4] =
                    make_float4(ms[0][j], ms[1][j], ms[2][j], ms[3][j]);
            }
        }
        asm volatile("bar.sync %0, 64;" :: "r"(bar) : "memory");

        // ---- P4: GEMM2  U[e][j] = sum_k ms[k][e] * c1[k][j]; partial g ----
        {
            ull b0 = *(const ull*)&s_cb1[og*8+0];
            ull b1 = *(const ull*)&s_cb1[og*8+2];
            ull b2 = *(const ull*)&s_cb1[og*8+4];
            ull b3 = *(const ull*)&s_cb1[og*8+6];
            #pragma unroll
            for (int e4=0;e4<4;e4++){ acc[e4*4]=b0; acc[e4*4+1]=b1; acc[e4*4+2]=b2; acc[e4*4+3]=b3; }
            const float* tp = s_t + eg*4;
            const float* wk = s_c1 + og*8;
            #pragma unroll 8
            for (int k=0;k<64;k++){
                float4 tv = *(const float4*)(tp + k*RL3);
                ulonglong2 wa = *(const ulonglong2*)(wk + k*64);
                ulonglong2 wb = *(const ulonglong2*)(wk + k*64 + 4);
                ull t0 = pack2(tv.x,tv.x), t1 = pack2(tv.y,tv.y);
                ull t2 = pack2(tv.z,tv.z), t3 = pack2(tv.w,tv.w);
                fma2(acc[0],  t0, wa.x); fma2(acc[1],  t0, wa.y); fma2(acc[2],  t0, wb.x); fma2(acc[3],  t0, wb.y);
                fma2(acc[4],  t1, wa.x); fma2(acc[5],  t1, wa.y); fma2(acc[6],  t1, wb.x); fma2(acc[7],  t1, wb.y);
                fma2(acc[8],  t2, wa.x); fma2(acc[9],  t2, wa.y); fma2(acc[10], t2, wb.x); fma2(acc[11], t2, wb.y);
                fma2(acc[12], t3, wa.x); fma2(acc[13], t3, wa.y); fma2(acc[14], t3, wb.x); fma2(acc[15], t3, wb.y);
            }
            float gp[4];
            #pragma unroll
            for (int e4=0;e4<4;e4++){
                float s = 0.f;
                #pragma unroll
                for (int jp=0;jp<4;jp++){
                    float2 f = unpack2(acc[e4*4+jp]);
                    s += silu_f(f.x)*s_cw2[og*8+2*jp] + silu_f(f.y)*s_cw2[og*8+2*jp+1];
                }
                gp[e4] = s;
            }
            *(float4*)&s_gp[og*32 + eg*4] = make_float4(gp[0],gp[1],gp[2],gp[3]);
        }
        asm volatile("bar.sync %0, 64;" :: "r"(bar) : "memory");

        // ---- P5: reduce g across out-groups, scatter coords ----
        if (gtid < 32){
            float gg = 0.f;
            #pragma unroll
            for (int o=0;o<8;o++) gg += s_gp[o*32 + gtid];
            int r = s_r[gtid];
            red4(&g_cagg4[r*4], s_dx[gtid]*gg, s_dy[gtid]*gg, s_dz[gtid]*gg, 0.f);
        }
        asm volatile("bar.sync %0, 64;" :: "r"(bar) : "memory");
    }
}

// -------- fused node MLP + state update ------------------------------------------
__global__ void k_node(const float* __restrict__ n_w1, const float* __restrict__ n_b1,
                       const float* __restrict__ n_w2, const float* __restrict__ n_b2){
    extern __shared__ float sn[];
    float* s_w1 = sn;           // 128x64
    float* s_w2 = sn + 8192;    // 64x64
    float* s_b1 = sn + 12288;
    float* s_b2 = sn + 12352;
    int tid = threadIdx.x;
    for (int i=tid; i<8192; i+=blockDim.x) s_w1[i] = n_w1[i];
    for (int i=tid; i<4096; i+=blockDim.x) s_w2[i] = n_w2[i];
    if (tid < 64){ s_b1[tid]=n_b1[tid]; s_b2[tid]=n_b2[tid]; }
    __syncthreads();
    int lane = tid & 31, warp = tid >> 5;
    int j0 = 2*lane;
    int wpb = blockDim.x >> 5;
    for (int n = blockIdx.x*wpb + warp; n < NN; n += gridDim.x*wpb){
        float h0 = g_h[n*H+j0],    h1 = g_h[n*H+j0+1];
        float m0 = g_magg[n*H+j0], m1 = g_magg[n*H+j0+1];
        float u0 = s_b1[j0], u1 = s_b1[j0+1];
        #pragma unroll
        for (int k=0;k<H;k++){
            float hk = __shfl_sync(0xffffffffu, (k&1)?h1:h0, k>>1);
            float mk = __shfl_sync(0xffffffffu, (k&1)?m1:m0, k>>1);
            float2 w1 = *(const float2*)&s_w1[k*H+j0];
            float2 w2 = *(const float2*)&s_w1[(H+k)*H+j0];
            u0 += hk*w1.x + mk*w2.x;
            u1 += hk*w1.y + mk*w2.y;
        }
        u0 = silu_f(u0); u1 = silu_f(u1);
        float a0 = s_b2[j0], a1 = s_b2[j0+1];
        #pragma unroll
        for (int k=0;k<H;k++){
            float uk = __shfl_sync(0xffffffffu, (k&1)?u1:u0, k>>1);
            float2 w = *(const float2*)&s_w2[k*H+j0];
            a0 += uk*w.x; a1 += uk*w.y;
        }
        *(float2*)&g_h[n*H+j0] = make_float2(2.f*h0 + a0, 2.f*h1 + a1);
        if (lane < 3){
            float dg = g_deg[n];
            float cm = g_cagg4[n*4+lane] / dg;
            float vi = g_v4[n*4+lane];
            float vn = vi + cm + g_vel[n]*vi;
            g_v4[n*4+lane] = vn;
            g_x4[n*4+lane] += vn;
        }
    }
}

// ---------------- output: [x | h | v] ---------------------------------------------
__global__ void k_out(float* __restrict__ out){
    int i = blockIdx.x*blockDim.x + threadIdx.x;
    if (i < NN*3){
        int n = i/3, d = i - n*3;
        out[i] = g_x4[n*4+d];
    } else if (i < NN*3+NN*H){
        out[i] = g_h[i-NN*3];
    } else if (i < NN*(6+H)){
        int j = i - NN*3 - NN*H;
        int n = j/3, d = j - n*3;
        out[i] = g_v4[n*4+d];
    }
}

extern "C" void kernel_launch(void* const* d_in, const int* in_sizes, int n_in,
                              void* d_out, int out_size){
    const float* his  = (const float*)d_in[0];
    const float* x    = (const float*)d_in[1];
    const float* v    = (const float*)d_in[2];
    const float* edge_attr = (const float*)d_in[3];
    const int*   edges= (const int*)  d_in[4];
    const float* emb_w= (const float*)d_in[5];
    const float* emb_b= (const float*)d_in[6];
    const float* e_w1 = (const float*)d_in[7];
    const float* e_b1 = (const float*)d_in[8];
    const float* e_w2 = (const float*)d_in[9];
    const float* e_b2 = (const float*)d_in[10];
    const float* c_w1 = (const float*)d_in[11];
    const float* c_b1 = (const float*)d_in[12];
    const float* c_w2 = (const float*)d_in[13];
    const float* n_w1 = (const float*)d_in[14];
    const float* n_b1 = (const float*)d_in[15];
    const float* n_w2 = (const float*)d_in[16];
    const float* n_b2 = (const float*)d_in[17];
    const float* v_w1 = (const float*)d_in[18];
    const float* v_b1 = (const float*)d_in[19];
    const float* v_w2 = (const float*)d_in[20];
    const float* v_b2 = (const float*)d_in[21];

    const int PREVEL_SMEM = 12480*4;
    const int NODE_SMEM   = 12416*4;
    const int EDGE_SMEM   = 18304*4;   // 73216 B
    cudaFuncSetAttribute(k_prevel, cudaFuncAttributeMaxDynamicSharedMemorySize, PREVEL_SMEM);
    cudaFuncSetAttribute(k_node,   cudaFuncAttributeMaxDynamicSharedMemorySize, NODE_SMEM);
    cudaFuncSetAttribute(k_edge,   cudaFuncAttributeMaxDynamicSharedMemorySize, EDGE_SMEM);

    k_init<<<(NN*H+255)/256, 256>>>(his, emb_w, emb_b, x, v);
    k_deg<<<(EE+255)/256, 256>>>(edges);
    k_scan<<<1, 1024>>>();
    k_fill<<<(EE+255)/256, 256>>>(edges, edge_attr);

    const int gn = 1184;
    const int ge = 444;    // 148 SMs x 3 resident blocks (= 1776 tile groups)

    for (int l=0; l<3; l++){
        k_prevel<<<gn, 256, PREVEL_SMEM>>>(e_w1, e_b1, v_w1, v_b1, v_w2, v_b2);
        k_edge<<<ge, TTH, EDGE_SMEM>>>(e_w1, e_w2, e_b2, c_w1, c_b1, c_w2);
        k_node<<<gn, 256, NODE_SMEM>>>(n_w1, n_b1, n_w2, n_b2);
    }
    k_out<<<(NN*(H+6)+255)/256, 256>>>((float*)d_out);
}

// round 7
// speedup vs baseline: 1.7832x; 1.0062x over previous
#include <cuda_runtime.h>

#define NN 50000
#define EE 1600000
#define H  64
#define TG  32      // edges per group-tile
#define NGB 4       // groups per block
#define TTH 256     // threads per edge block
#define RL3 32      // s_t row length
#define NTG (EE/TG) // 50000 group-tiles

typedef unsigned long long ull;

// ---------------- scratch (device globals; no allocation allowed) ----------------
__device__ float g_h[NN*H];
__device__ float g_A[NN*H];      // h@Wa + e_b1
__device__ float g_B[NN*H];      // h@Wb
__device__ float g_magg[NN*H];   // segment-summed messages
__device__ float g_cagg4[NN*4];  // segment-summed coord updates (padded)
__device__ float g_vel[NN];      // vel_scale
__device__ float g_deg[NN];      // clipped out-degree (float)
__device__ int   g_cnt[NN];      // raw out-degree
__device__ int   g_off[NN];      // fill cursors
__device__ float g_x4[NN*4];     // padded coords
__device__ float g_v4[NN*4];     // padded velocities
// r-sorted edge arrays
__device__ int    g_er[EE];
__device__ int    g_ec[EE];
__device__ float2 g_ea2[EE];

__device__ __forceinline__ float silu_f(float x){
    float th;
    asm("tanh.approx.f32 %0, %1;" : "=f"(th) : "f"(0.5f*x));
    return 0.5f*x*th + 0.5f*x;
}
__device__ __forceinline__ ull pack2(float x, float y){
    ull r; asm("mov.b64 %0, {%1,%2};" : "=l"(r) : "f"(x), "f"(y)); return r;
}
__device__ __forceinline__ float2 unpack2(ull p){
    float2 r; asm("mov.b64 {%0,%1}, %2;" : "=f"(r.x), "=f"(r.y) : "l"(p)); return r;
}
__device__ __forceinline__ void fma2(ull& d, ull a, ull b){
    asm("fma.rn.f32x2 %0, %1, %2, %0;" : "+l"(d) : "l"(a), "l"(b));
}
__device__ __forceinline__ void red4(float* p, float a, float b, float c, float d){
    asm volatile("red.global.add.v4.f32 [%0], {%1,%2,%3,%4};"
                 :: "l"(p), "f"(a), "f"(b), "f"(c), "f"(d) : "memory");
}
__device__ __forceinline__ void pf_l1(const float* p){
    asm volatile("prefetch.global.L1 [%0];" :: "l"(p));
}

// ---------------- init ------------------------------------------------------------
__global__ void k_init(const float* __restrict__ his, const float* __restrict__ emb_w,
                       const float* __restrict__ emb_b, const float* __restrict__ x,
                       const float* __restrict__ v){
    int idx = blockIdx.x*blockDim.x + threadIdx.x;
    if (idx < NN*H){
        int n = idx >> 6, j = idx & 63;
        float acc = emb_b[j];
        #pragma unroll
        for (int k=0;k<16;k++) acc += his[n*16+k]*emb_w[k*H+j];
        g_h[idx] = acc;
    }
    if (idx < NN){
        g_x4[idx*4+0]=x[idx*3+0]; g_x4[idx*4+1]=x[idx*3+1]; g_x4[idx*4+2]=x[idx*3+2]; g_x4[idx*4+3]=0.f;
        g_v4[idx*4+0]=v[idx*3+0]; g_v4[idx*4+1]=v[idx*3+1]; g_v4[idx*4+2]=v[idx*3+2]; g_v4[idx*4+3]=0.f;
        g_cnt[idx] = 0;
    }
}

__global__ void k_deg(const int* __restrict__ edges){
    int e = blockIdx.x*blockDim.x + threadIdx.x;
    if (e < EE) atomicAdd(&g_cnt[edges[e]], 1);
}

// single-block exclusive scan over g_cnt -> g_off; also g_deg = max(cnt,1)
__global__ void k_scan(){
    __shared__ int s_part[1024];
    int tid = threadIdx.x;
    const int CH = (NN + 1023)/1024;   // 49
    int base = tid*CH;
    int sum = 0;
    #pragma unroll 7
    for (int i=0;i<CH;i++){ int n=base+i; if(n<NN) sum += g_cnt[n]; }
    s_part[tid] = sum;
    __syncthreads();
    for (int off=1; off<1024; off<<=1){
        int t = (tid >= off) ? s_part[tid-off] : 0;
        __syncthreads();
        s_part[tid] += t;
        __syncthreads();
    }
    int run = s_part[tid] - sum;
    for (int i=0;i<CH;i++){
        int n = base+i;
        if (n < NN){
            int c = g_cnt[n];
            g_off[n] = run;
            g_deg[n] = (c > 0) ? (float)c : 1.0f;
            run += c;
        }
    }
}

__global__ void k_fill(const int* __restrict__ edges, const float* __restrict__ edge_attr){
    int e = blockIdx.x*blockDim.x + threadIdx.x;
    if (e < EE){
        int r = edges[e];
        int pos = atomicAdd(&g_off[r], 1);
        g_er[pos] = r;
        g_ec[pos] = edges[EE+e];
        g_ea2[pos] = ((const float2*)edge_attr)[e];
    }
}

// ------ fused per-layer node precompute: A,B, vel_scale; zero aggs ----------------
__global__ void k_prevel(const float* __restrict__ e_w1, const float* __restrict__ e_b1,
                         const float* __restrict__ v_w1, const float* __restrict__ v_b1,
                         const float* __restrict__ v_w2, const float* __restrict__ v_b2){
    extern __shared__ float sp[];
    float* s_ew  = sp;            // 128x64
    float* s_vw  = sp + 8192;     // 64x64
    float* s_eb1 = sp + 12288;
    float* s_vb1 = sp + 12352;
    float* s_vw2 = sp + 12416;
    int tid = threadIdx.x;
    for (int i=tid; i<8192; i+=blockDim.x) s_ew[i] = e_w1[i];
    for (int i=tid; i<4096; i+=blockDim.x) s_vw[i] = v_w1[i];
    if (tid < 64){ s_eb1[tid]=e_b1[tid]; s_vb1[tid]=v_b1[tid]; s_vw2[tid]=v_w2[tid]; }
    __syncthreads();
    int lane = tid & 31, warp = tid >> 5;
    int j0 = 2*lane;
    int wpb = blockDim.x >> 5;
    float vb2 = v_b2[0];
    for (int n = blockIdx.x*wpb + warp; n < NN; n += gridDim.x*wpb){
        float h0 = g_h[n*H+j0], h1 = g_h[n*H+j0+1];
        float a0 = s_eb1[j0], a1 = s_eb1[j0+1];
        float b0 = 0.f, b1 = 0.f;
        float t0 = s_vb1[j0], t1 = s_vb1[j0+1];
        #pragma unroll
        for (int k=0;k<H;k++){
            float hk = __shfl_sync(0xffffffffu, (k&1)?h1:h0, k>>1);
            float2 wa = *(const float2*)&s_ew[k*H+j0];
            float2 wb = *(const float2*)&s_ew[(H+k)*H+j0];
            float2 wv = *(const float2*)&s_vw[k*H+j0];
            a0 += hk*wa.x; a1 += hk*wa.y;
            b0 += hk*wb.x; b1 += hk*wb.y;
            t0 += hk*wv.x; t1 += hk*wv.y;
        }
        *(float2*)&g_A[n*H+j0]    = make_float2(a0,a1);
        *(float2*)&g_B[n*H+j0]    = make_float2(b0,b1);
        *(float2*)&g_magg[n*H+j0] = make_float2(0.f,0.f);
        float p = silu_f(t0)*s_vw2[j0] + silu_f(t1)*s_vw2[j0+1];
        #pragma unroll
        for (int o=16;o>0;o>>=1) p += __shfl_xor_sync(0xffffffffu, p, o);
        if (lane == 0){
            g_vel[n] = p + vb2;
            *(float4*)&g_cagg4[n*4] = make_float4(0.f,0.f,0.f,0.f);
        }
    }
}

// ------- edge kernel: 4x64-thread groups, 32-edge r-sorted tiles, run-agg scatter -
__global__ void __launch_bounds__(TTH, 3)
k_edge(const float* __restrict__ e_w1, const float* __restrict__ e_w2,
       const float* __restrict__ e_b2, const float* __restrict__ c_w1,
       const float* __restrict__ c_b1, const float* __restrict__ c_w2){
    extern __shared__ float sm[];
    float* s_w2  = sm;              // 4096 (block-shared, read-only)
    float* s_c1  = sm + 4096;       // 4096
    float* s_wr  = sm + 8192;       // 64
    float* s_we0 = sm + 8256;
    float* s_we1 = sm + 8320;
    float* s_eb2 = sm + 8384;
    float* s_cb1 = sm + 8448;
    float* s_cw2 = sm + 8512;       // .. 8576
    int tid = threadIdx.x;
    int g    = tid >> 6;            // group 0..3
    int gtid = tid & 63;
    float* gb   = sm + 8576 + g*2432;
    float* s_t  = gb;               // 64*RL3 = 2048
    float* s_gp = gb + 2048;        // 8*32 = 256
    float* s_dx = gb + 2304;        // 32
    float* s_dy = gb + 2336;
    float* s_dz = gb + 2368;
    int*   s_r  = (int*)(gb + 2400);// 32

    for (int i=tid; i<4096; i+=TTH){ s_w2[i] = e_w2[i]; s_c1[i] = c_w1[i]; }
    if (tid < 64){
        s_wr [tid] = e_w1[128*H+tid];
        s_we0[tid] = e_w1[129*H+tid];
        s_we1[tid] = e_w1[130*H+tid];
        s_eb2[tid] = e_b2[tid];
        s_cb1[tid] = c_b1[tid];
        s_cw2[tid] = c_w2[tid];
    }
    __syncthreads();

    int el = gtid & 31, hf = gtid >> 5;   // P1 mapping (2 threads/edge)
    int eg = gtid & 7,  og = gtid >> 3;   // GEMM mapping: 4 edges x 8 outputs
    int bar = g + 1;
    const int estep = gridDim.x*NGB*TG;

    for (int tile = blockIdx.x*NGB + g; tile < NTG; tile += gridDim.x*NGB){
        // ---- P1: gather + first-layer pre + silu -> s_t[k][e]; prefetch next ----
        {
            int e = tile*TG + el;
            int r = g_er[e], c = g_ec[e];
            // prefetch next tile's A/B half-rows into L1
            int en = e + estep;
            if (en < EE){
                int rn = g_er[en], cn = g_ec[en];
                pf_l1(g_A + rn*H + hf*32);
                pf_l1(g_B + cn*H + hf*32);
            }
            float4 xr = *(const float4*)&g_x4[r*4];
            float4 xc = *(const float4*)&g_x4[c*4];
            float dx = xr.x-xc.x, dy = xr.y-xc.y, dz = xr.z-xc.z;
            float radial = dx*dx + dy*dy + dz*dz;
            float2 ea = g_ea2[e];
            const float4* Ap = (const float4*)(g_A + r*H + hf*32);
            const float4* Bp = (const float4*)(g_B + c*H + hf*32);
            int kb = hf*32;
            #pragma unroll
            for (int q=0;q<8;q++){
                float4 a = Ap[q], b = Bp[q];
                int k = kb + 4*q;
                float4 w1 = *(const float4*)&s_wr [k];
                float4 w2 = *(const float4*)&s_we0[k];
                float4 w3 = *(const float4*)&s_we1[k];
                s_t[(k+0)*RL3+el] = silu_f(a.x + b.x + radial*w1.x + ea.x*w2.x + ea.y*w3.x);
                s_t[(k+1)*RL3+el] = silu_f(a.y + b.y + radial*w1.y + ea.x*w2.y + ea.y*w3.y);
                s_t[(k+2)*RL3+el] = silu_f(a.z + b.z + radial*w1.z + ea.x*w2.z + ea.y*w3.z);
                s_t[(k+3)*RL3+el] = silu_f(a.w + b.w + radial*w1.w + ea.x*w2.w + ea.y*w3.w);
            }
            if (!hf){ s_r[el]=r; s_dx[el]=dx; s_dy[el]=dy; s_dz[el]=dz; }
        }
        asm volatile("bar.sync %0, 64;" :: "r"(bar) : "memory");

        // ---- P2: GEMM1  M[e][j] = sum_k s_t[k][e] * w2[k][j] ----
        ull acc[16];
        {
            ull b0 = *(const ull*)&s_eb2[og*8+0];
            ull b1 = *(const ull*)&s_eb2[og*8+2];
            ull b2 = *(const ull*)&s_eb2[og*8+4];
            ull b3 = *(const ull*)&s_eb2[og*8+6];
            #pragma unroll
            for (int e4=0;e4<4;e4++){ acc[e4*4]=b0; acc[e4*4+1]=b1; acc[e4*4+2]=b2; acc[e4*4+3]=b3; }
            const float* tp = s_t + eg*4;
            const float* wk = s_w2 + og*8;
            #pragma unroll 8
            for (int k=0;k<64;k++){
                float4 tv = *(const float4*)(tp + k*RL3);
                ulonglong2 wa = *(const ulonglong2*)(wk + k*64);
                ulonglong2 wb = *(const ulonglong2*)(wk + k*64 + 4);
                ull t0 = pack2(tv.x,tv.x), t1 = pack2(tv.y,tv.y);
                ull t2 = pack2(tv.z,tv.z), t3 = pack2(tv.w,tv.w);
                fma2(acc[0],  t0, wa.x); fma2(acc[1],  t0, wa.y); fma2(acc[2],  t0, wb.x); fma2(acc[3],  t0, wb.y);
                fma2(acc[4],  t1, wa.x); fma2(acc[5],  t1, wa.y); fma2(acc[6],  t1, wb.x); fma2(acc[7],  t1, wb.y);
                fma2(acc[8],  t2, wa.x); fma2(acc[9],  t2, wa.y); fma2(acc[10], t2, wb.x); fma2(acc[11], t2, wb.y);
                fma2(acc[12], t3, wa.x); fma2(acc[13], t3, wa.y); fma2(acc[14], t3, wb.x); fma2(acc[15], t3, wb.y);
            }
        }
        asm volatile("bar.sync %0, 64;" :: "r"(bar) : "memory");

        // ---- P3: silu(M), store ms -> s_t[j][e], run-aggregated scatter to m_agg -
        {
            float ms[4][8];
            #pragma unroll
            for (int e4=0;e4<4;e4++){
                #pragma unroll
                for (int jp=0;jp<4;jp++){
                    float2 f = unpack2(acc[e4*4+jp]);
                    ms[e4][2*jp]   = silu_f(f.x);
                    ms[e4][2*jp+1] = silu_f(f.y);
                }
            }
            #pragma unroll
            for (int j=0;j<8;j++){
                *(float4*)&s_t[(og*8+j)*RL3 + eg*4] =
                    make_float4(ms[0][j], ms[1][j], ms[2][j], ms[3][j]);
            }
            // run aggregation over the 4 consecutive sorted edges (in place)
            int r0 = s_r[eg*4+0], r1 = s_r[eg*4+1], r2 = s_r[eg*4+2], r3 = s_r[eg*4+3];
            int rh = 0;
            int rr[4] = {r0,r1,r2,r3};
            #pragma unroll
            for (int e4=1;e4<4;e4++){
                if (rr[e4] == rr[rh]){
                    #pragma unroll
                    for (int j=0;j<8;j++) ms[rh][j] += ms[e4][j];
                } else {
                    float* mp = &g_magg[rr[rh]*H + og*8];
                    red4(mp,   ms[rh][0], ms[rh][1], ms[rh][2], ms[rh][3]);
                    red4(mp+4, ms[rh][4], ms[rh][5], ms[rh][6], ms[rh][7]);
                    rh = e4;
                }
            }
            float* mp = &g_magg[rr[rh]*H + og*8];
            red4(mp,   ms[rh][0], ms[rh][1], ms[rh][2], ms[rh][3]);
            red4(mp+4, ms[rh][4], ms[rh][5], ms[rh][6], ms[rh][7]);
        }
        asm volatile("bar.sync %0, 64;" :: "r"(bar) : "memory");

        // ---- P4: GEMM2  U[e][j] = sum_k ms[k][e] * c1[k][j]; partial g ----
        {
            ull b0 = *(const ull*)&s_cb1[og*8+0];
            ull b1 = *(const ull*)&s_cb1[og*8+2];
            ull b2 = *(const ull*)&s_cb1[og*8+4];
            ull b3 = *(const ull*)&s_cb1[og*8+6];
            #pragma unroll
            for (int e4=0;e4<4;e4++){ acc[e4*4]=b0; acc[e4*4+1]=b1; acc[e4*4+2]=b2; acc[e4*4+3]=b3; }
            const float* tp = s_t + eg*4;
            const float* wk = s_c1 + og*8;
            #pragma unroll 8
            for (int k=0;k<64;k++){
                float4 tv = *(const float4*)(tp + k*RL3);
                ulonglong2 wa = *(const ulonglong2*)(wk + k*64);
                ulonglong2 wb = *(const ulonglong2*)(wk + k*64 + 4);
                ull t0 = pack2(tv.x,tv.x), t1 = pack2(tv.y,tv.y);
                ull t2 = pack2(tv.z,tv.z), t3 = pack2(tv.w,tv.w);
                fma2(acc[0],  t0, wa.x); fma2(acc[1],  t0, wa.y); fma2(acc[2],  t0, wb.x); fma2(acc[3],  t0, wb.y);
                fma2(acc[4],  t1, wa.x); fma2(acc[5],  t1, wa.y); fma2(acc[6],  t1, wb.x); fma2(acc[7],  t1, wb.y);
                fma2(acc[8],  t2, wa.x); fma2(acc[9],  t2, wa.y); fma2(acc[10], t2, wb.x); fma2(acc[11], t2, wb.y);
                fma2(acc[12], t3, wa.x); fma2(acc[13], t3, wa.y); fma2(acc[14], t3, wb.x); fma2(acc[15], t3, wb.y);
            }
            float gp[4];
            #pragma unroll
            for (int e4=0;e4<4;e4++){
                float s = 0.f;
                #pragma unroll
                for (int jp=0;jp<4;jp++){
                    float2 f = unpack2(acc[e4*4+jp]);
                    s += silu_f(f.x)*s_cw2[og*8+2*jp] + silu_f(f.y)*s_cw2[og*8+2*jp+1];
                }
                gp[e4] = s;
            }
            *(float4*)&s_gp[og*32 + eg*4] = make_float4(gp[0],gp[1],gp[2],gp[3]);
        }
        asm volatile("bar.sync %0, 64;" :: "r"(bar) : "memory");

        // ---- P5: reduce g across out-groups; segmented coord scatter ----
        if (gtid < 32){
            float gg = 0.f;
            #pragma unroll
            for (int o=0;o<8;o++) gg += s_gp[o*32 + gtid];
            int r = s_r[gtid];
            float cx = s_dx[gtid]*gg, cy = s_dy[gtid]*gg, cz = s_dz[gtid]*gg;
            // warp-segmented suffix reduce (keys sorted: endpoint eq => segment eq)
            unsigned fm = 0xffffffffu;
            #pragma unroll
            for (int off=1; off<32; off<<=1){
                int ro   = __shfl_down_sync(fm, r,  off);
                float xo = __shfl_down_sync(fm, cx, off);
                float yo = __shfl_down_sync(fm, cy, off);
                float zo = __shfl_down_sync(fm, cz, off);
                if (gtid + off < 32 && ro == r){ cx += xo; cy += yo; cz += zo; }
            }
            int rp = __shfl_up_sync(fm, r, 1);
            if (gtid == 0 || rp != r)
                red4(&g_cagg4[r*4], cx, cy, cz, 0.f);
        }
        asm volatile("bar.sync %0, 64;" :: "r"(bar) : "memory");
    }
}

// -------- fused node MLP + state update ------------------------------------------
__global__ void k_node(const float* __restrict__ n_w1, const float* __restrict__ n_b1,
                       const float* __restrict__ n_w2, const float* __restrict__ n_b2){
    extern __shared__ float sn[];
    float* s_w1 = sn;           // 128x64
    float* s_w2 = sn + 8192;    // 64x64
    float* s_b1 = sn + 12288;
    float* s_b2 = sn + 12352;
    int tid = threadIdx.x;
    for (int i=tid; i<8192; i+=blockDim.x) s_w1[i] = n_w1[i];
    for (int i=tid; i<4096; i+=blockDim.x) s_w2[i] = n_w2[i];
    if (tid < 64){ s_b1[tid]=n_b1[tid]; s_b2[tid]=n_b2[tid]; }
    __syncthreads();
    int lane = tid & 31, warp = tid >> 5;
    int j0 = 2*lane;
    int wpb = blockDim.x >> 5;
    for (int n = blockIdx.x*wpb + warp; n < NN; n += gridDim.x*wpb){
        float h0 = g_h[n*H+j0],    h1 = g_h[n*H+j0+1];
        float m0 = g_magg[n*H+j0], m1 = g_magg[n*H+j0+1];
        float u0 = s_b1[j0], u1 = s_b1[j0+1];
        #pragma unroll
        for (int k=0;k<H;k++){
            float hk = __shfl_sync(0xffffffffu, (k&1)?h1:h0, k>>1);
            float mk = __shfl_sync(0xffffffffu, (k&1)?m1:m0, k>>1);
            float2 w1 = *(const float2*)&s_w1[k*H+j0];
            float2 w2 = *(const float2*)&s_w1[(H+k)*H+j0];
            u0 += hk*w1.x + mk*w2.x;
            u1 += hk*w1.y + mk*w2.y;
        }
        u0 = silu_f(u0); u1 = silu_f(u1);
        float a0 = s_b2[j0], a1 = s_b2[j0+1];
        #pragma unroll
        for (int k=0;k<H;k++){
            float uk = __shfl_sync(0xffffffffu, (k&1)?u1:u0, k>>1);
            float2 w = *(const float2*)&s_w2[k*H+j0];
            a0 += uk*w.x; a1 += uk*w.y;
        }
        *(float2*)&g_h[n*H+j0] = make_float2(2.f*h0 + a0, 2.f*h1 + a1);
        if (lane < 3){
            float dg = g_deg[n];
            float cm = g_cagg4[n*4+lane] / dg;
            float vi = g_v4[n*4+lane];
            float vn = vi + cm + g_vel[n]*vi;
            g_v4[n*4+lane] = vn;
            g_x4[n*4+lane] += vn;
        }
    }
}

// ---------------- output: [x | h | v] ---------------------------------------------
__global__ void k_out(float* __restrict__ out){
    int i = blockIdx.x*blockDim.x + threadIdx.x;
    if (i < NN*3){
        int n = i/3, d = i - n*3;
        out[i] = g_x4[n*4+d];
    } else if (i < NN*3+NN*H){
        out[i] = g_h[i-NN*3];
    } else if (i < NN*(6+H)){
        int j = i - NN*3 - NN*H;
        int n = j/3, d = j - n*3;
        out[i] = g_v4[n*4+d];
    }
}

extern "C" void kernel_launch(void* const* d_in, const int* in_sizes, int n_in,
                              void* d_out, int out_size){
    const float* his  = (const float*)d_in[0];
    const float* x    = (const float*)d_in[1];
    const float* v    = (const float*)d_in[2];
    const float* edge_attr = (const float*)d_in[3];
    const int*   edges= (const int*)  d_in[4];
    const float* emb_w= (const float*)d_in[5];
    const float* emb_b= (const float*)d_in[6];
    const float* e_w1 = (const float*)d_in[7];
    const float* e_b1 = (const float*)d_in[8];
    const float* e_w2 = (const float*)d_in[9];
    const float* e_b2 = (const float*)d_in[10];
    const float* c_w1 = (const float*)d_in[11];
    const float* c_b1 = (const float*)d_in[12];
    const float* c_w2 = (const float*)d_in[13];
    const float* n_w1 = (const float*)d_in[14];
    const float* n_b1 = (const float*)d_in[15];
    const float* n_w2 = (const float*)d_in[16];
    const float* n_b2 = (const float*)d_in[17];
    const float* v_w1 = (const float*)d_in[18];
    const float* v_b1 = (const float*)d_in[19];
    const float* v_w2 = (const float*)d_in[20];
    const float* v_b2 = (const float*)d_in[21];

    const int PREVEL_SMEM = 12480*4;
    const int NODE_SMEM   = 12416*4;
    const int EDGE_SMEM   = 18304*4;   // 73216 B
    cudaFuncSetAttribute(k_prevel, cudaFuncAttributeMaxDynamicSharedMemorySize, PREVEL_SMEM);
    cudaFuncSetAttribute(k_node,   cudaFuncAttributeMaxDynamicSharedMemorySize, NODE_SMEM);
    cudaFuncSetAttribute(k_edge,   cudaFuncAttributeMaxDynamicSharedMemorySize, EDGE_SMEM);

    k_init<<<(NN*H+255)/256, 256>>>(his, emb_w, emb_b, x, v);
    k_deg<<<(EE+255)/256, 256>>>(edges);
    k_scan<<<1, 1024>>>();
    k_fill<<<(EE+255)/256, 256>>>(edges, edge_attr);

    const int gn = 1184;
    const int ge = 444;

    for (int l=0; l<3; l++){
        k_prevel<<<gn, 256, PREVEL_SMEM>>>(e_w1, e_b1, v_w1, v_b1, v_w2, v_b2);
        k_edge<<<ge, TTH, EDGE_SMEM>>>(e_w1, e_w2, e_b2, c_w1, c_b1, c_w2);
        k_node<<<gn, 256, NODE_SMEM>>>(n_w1, n_b1, n_w2, n_b2);
    }
    k_out<<<(NN*(H+6)+255)/256, 256>>>((float*)d_out);
}